// round 5
// baseline (speedup 1.0000x reference)
#include <cuda_runtime.h>
#include <cuda_bf16.h>

// GCN 2-layer, CSR-gather formulation:
//   h1 = X@W1 ; agg1 = Ahat·h1 + b1 ; h2 = relu(agg1)@W2 ; out = Ahat·h2 + b2
//   Ahat = D^{-1/2}(A+I)D^{-1/2}; agg via per-dst warp gather (no float atomics)

#define NMAX   100000
#define EMAX   1600000
#define IN_CH  128
#define HID    64
#define OUTC   32

typedef unsigned long long ull;

__device__ int   g_cnt[NMAX];          // real in-degree (no self loop)
__device__ int   g_off[NMAX + 1];      // CSR offsets
__device__ int   g_cur[NMAX];          // scatter cursors
__device__ int   g_csrc[EMAX];         // CSR src lists grouped by dst
__device__ float g_dis[NMAX];          // deg^{-1/2} (deg incl self loop)
__device__ float g_h1 [NMAX * HID];
__device__ float g_agg1[NMAX * HID];
__device__ float g_h2 [NMAX * OUTC];

// packed dual-fp32 FMA
__device__ __forceinline__ void fma2(ull& acc, ull a, ull b) {
    asm("fma.rn.f32x2 %0, %1, %2, %0;" : "+l"(acc) : "l"(a), "l"(b));
}
__device__ __forceinline__ float unpack_sum(ull v) {
    float2 f;
    asm("mov.b64 {%0, %1}, %2;" : "=f"(f.x), "=f"(f.y) : "l"(v));
    return f.x + f.y;
}

// ---------------- CSR build ----------------

__global__ void k_zero(int n) {
    int i = blockIdx.x * blockDim.x + threadIdx.x;
    if (i < n) g_cnt[i] = 0;
}

__global__ void k_count(const int* __restrict__ ei, int E) {
    int e = blockIdx.x * blockDim.x + threadIdx.x;
    if (e < E) atomicAdd(&g_cnt[ei[E + e]], 1);
}

// single block, 1024 threads: exclusive scan of g_cnt -> g_off/g_cur, plus dis
__global__ __launch_bounds__(1024) void k_scan(int n) {
    __shared__ int spart[1024];
    int t = threadIdx.x;
    int chunk = (n + 1023) >> 10;
    int lo = t * chunk;
    int hi = min(lo + chunk, n);
    int sum = 0;
    for (int i = lo; i < hi; i++) sum += g_cnt[i];
    spart[t] = sum;
    __syncthreads();
    for (int ofs = 1; ofs < 1024; ofs <<= 1) {
        int v = (t >= ofs) ? spart[t - ofs] : 0;
        __syncthreads();
        spart[t] += v;
        __syncthreads();
    }
    int run = (t == 0) ? 0 : spart[t - 1];
    for (int i = lo; i < hi; i++) {
        int c = g_cnt[i];
        g_off[i] = run;
        g_cur[i] = run;
        g_dis[i] = rsqrtf((float)(c + 1));
        run += c;
    }
    if (t == 1023) g_off[n] = spart[1023];
}

__global__ void k_scatter(const int* __restrict__ ei, int E) {
    int e = blockIdx.x * blockDim.x + threadIdx.x;
    if (e < E) {
        int s = ei[e];
        int d = ei[E + e];
        int pos = atomicAdd(&g_cur[d], 1);
        g_csrc[pos] = s;
    }
}

// ---------------- GEMM1: h1 = x @ W1 ----------------
// 64 nodes x 64 ch / block, 256 thr, f32x2 K-pairing.

#define KC 64

__global__ __launch_bounds__(256) void k_gemm1(const float* __restrict__ x,
                                               const float* __restrict__ W1,
                                               int n) {
    __shared__ float sx[64 * 66];
    __shared__ float sWp[(KC / 2) * 128];

    int tid = threadIdx.x;
    int base = blockIdx.x * 64;
    int ng = tid & 31;
    int cg = tid >> 5;

    ull acc[2][8];
#pragma unroll
    for (int i = 0; i < 2; i++)
#pragma unroll
        for (int j = 0; j < 8; j++) acc[i][j] = 0ull;

    for (int kc = 0; kc < IN_CH; kc += KC) {
        __syncthreads();
#pragma unroll
        for (int i = 0; i < 16; i++) {
            int idx = tid + 256 * i;
            int k = idx >> 6, c = idx & 63;
            sWp[(k >> 1) * 128 + c * 2 + (k & 1)] = W1[(kc + k) * HID + c];
        }
#pragma unroll
        for (int i = 0; i < 4; i++) {
            int f = tid + 256 * i;
            int node = f >> 4;
            int q = f & 15;
            int gn = base + node;
            float4 v = make_float4(0.f, 0.f, 0.f, 0.f);
            if (gn < n) v = reinterpret_cast<const float4*>(x + gn * IN_CH + kc)[q];
            float* r = sx + node * 66 + 4 * q;
            r[0] = v.x; r[1] = v.y; r[2] = v.z; r[3] = v.w;
        }
        __syncthreads();

#pragma unroll
        for (int k2 = 0; k2 < KC / 2; k2++) {
            ull xv0 = *reinterpret_cast<const ull*>(sx + ng * 66 + 2 * k2);
            ull xv1 = *reinterpret_cast<const ull*>(sx + (ng + 32) * 66 + 2 * k2);
            const ulonglong2* wr =
                reinterpret_cast<const ulonglong2*>(sWp + k2 * 128 + cg * 16);
            ulonglong2 wa = wr[0], wb = wr[1], wc = wr[2], wd = wr[3];
            fma2(acc[0][0], xv0, wa.x); fma2(acc[1][0], xv1, wa.x);
            fma2(acc[0][1], xv0, wa.y); fma2(acc[1][1], xv1, wa.y);
            fma2(acc[0][2], xv0, wb.x); fma2(acc[1][2], xv1, wb.x);
            fma2(acc[0][3], xv0, wb.y); fma2(acc[1][3], xv1, wb.y);
            fma2(acc[0][4], xv0, wc.x); fma2(acc[1][4], xv1, wc.x);
            fma2(acc[0][5], xv0, wc.y); fma2(acc[1][5], xv1, wc.y);
            fma2(acc[0][6], xv0, wd.x); fma2(acc[1][6], xv1, wd.x);
            fma2(acc[0][7], xv0, wd.y); fma2(acc[1][7], xv1, wd.y);
        }
    }

#pragma unroll
    for (int i = 0; i < 2; i++) {
        int node = base + ng + 32 * i;
        if (node >= n) continue;
        float4* oh = reinterpret_cast<float4*>(g_h1 + node * HID + cg * 8);
        oh[0] = make_float4(unpack_sum(acc[i][0]), unpack_sum(acc[i][1]),
                            unpack_sum(acc[i][2]), unpack_sum(acc[i][3]));
        oh[1] = make_float4(unpack_sum(acc[i][4]), unpack_sum(acc[i][5]),
                            unpack_sum(acc[i][6]), unpack_sum(acc[i][7]));
    }
}

// ---------------- layer-1 aggregation: warp per dst node ----------------
// agg1[d] = dd*( sum_s dis[s]*h1[s] + dd*h1[d] ) + b1,  lane holds 2 ch.

__global__ __launch_bounds__(256) void k_agg1(const float* __restrict__ b1, int n) {
    int warp = (blockIdx.x * blockDim.x + threadIdx.x) >> 5;
    int lane = threadIdx.x & 31;
    if (warp >= n) return;
    int d = warp;
    float dd = g_dis[d];
    int lo = g_off[d], hi = g_off[d + 1];

    float2 hs = *reinterpret_cast<const float2*>(g_h1 + d * HID + lane * 2);
    float a0x = dd * hs.x, a0y = dd * hs.y;
    float a1x = 0.f, a1y = 0.f;

    int j = lo;
    for (; j + 1 < hi; j += 2) {
        int s0 = g_csrc[j];
        int s1 = g_csrc[j + 1];
        float w0 = g_dis[s0];
        float w1 = g_dis[s1];
        float2 v0 = *reinterpret_cast<const float2*>(g_h1 + s0 * HID + lane * 2);
        float2 v1 = *reinterpret_cast<const float2*>(g_h1 + s1 * HID + lane * 2);
        a0x += w0 * v0.x; a0y += w0 * v0.y;
        a1x += w1 * v1.x; a1y += w1 * v1.y;
    }
    if (j < hi) {
        int s0 = g_csrc[j];
        float w0 = g_dis[s0];
        float2 v0 = *reinterpret_cast<const float2*>(g_h1 + s0 * HID + lane * 2);
        a0x += w0 * v0.x; a0y += w0 * v0.y;
    }

    float2 bb = *reinterpret_cast<const float2*>(b1 + lane * 2);
    float2 o;
    o.x = (a0x + a1x) * dd + bb.x;
    o.y = (a0y + a1y) * dd + bb.y;
    *reinterpret_cast<float2*>(g_agg1 + d * HID + lane * 2) = o;
}

// ---------------- GEMM2: h2 = relu(agg1) @ W2 ----------------
// 128 nodes x 32 ch / block, 256 thr, f32x2 K-pairing, relu fused at stage.

__global__ __launch_bounds__(256) void k_gemm2(const float* __restrict__ W2, int n) {
    __shared__ float sx[128 * 66];
    __shared__ float sWp[(HID / 2) * 64];

    int tid = threadIdx.x;
    int base = blockIdx.x * 128;
    int ng = tid & 31;
    int cg = tid >> 5;

#pragma unroll
    for (int i = 0; i < 8; i++) {
        int idx = tid + 256 * i;
        int k = idx >> 5, c = idx & 31;
        sWp[(k >> 1) * 64 + c * 2 + (k & 1)] = W2[k * OUTC + c];
    }
#pragma unroll
    for (int i = 0; i < 8; i++) {
        int f = tid + 256 * i;
        int node = f >> 4;
        int q = f & 15;
        int gn = base + node;
        float4 v = make_float4(0.f, 0.f, 0.f, 0.f);
        if (gn < n) {
            v = reinterpret_cast<const float4*>(g_agg1 + gn * HID)[q];
            v.x = fmaxf(v.x, 0.f); v.y = fmaxf(v.y, 0.f);
            v.z = fmaxf(v.z, 0.f); v.w = fmaxf(v.w, 0.f);
        }
        float* r = sx + node * 66 + 4 * q;
        r[0] = v.x; r[1] = v.y; r[2] = v.z; r[3] = v.w;
    }
    __syncthreads();

    ull acc[4][4];
#pragma unroll
    for (int i = 0; i < 4; i++)
#pragma unroll
        for (int j = 0; j < 4; j++) acc[i][j] = 0ull;

#pragma unroll
    for (int k2 = 0; k2 < HID / 2; k2++) {
        ull xv0 = *reinterpret_cast<const ull*>(sx + ng * 66 + 2 * k2);
        ull xv1 = *reinterpret_cast<const ull*>(sx + (ng + 32) * 66 + 2 * k2);
        ull xv2 = *reinterpret_cast<const ull*>(sx + (ng + 64) * 66 + 2 * k2);
        ull xv3 = *reinterpret_cast<const ull*>(sx + (ng + 96) * 66 + 2 * k2);
        const ulonglong2* wr =
            reinterpret_cast<const ulonglong2*>(sWp + k2 * 64 + cg * 8);
        ulonglong2 wa = wr[0], wb = wr[1];
        fma2(acc[0][0], xv0, wa.x); fma2(acc[1][0], xv1, wa.x);
        fma2(acc[2][0], xv2, wa.x); fma2(acc[3][0], xv3, wa.x);
        fma2(acc[0][1], xv0, wa.y); fma2(acc[1][1], xv1, wa.y);
        fma2(acc[2][1], xv2, wa.y); fma2(acc[3][1], xv3, wa.y);
        fma2(acc[0][2], xv0, wb.x); fma2(acc[1][2], xv1, wb.x);
        fma2(acc[2][2], xv2, wb.x); fma2(acc[3][2], xv3, wb.x);
        fma2(acc[0][3], xv0, wb.y); fma2(acc[1][3], xv1, wb.y);
        fma2(acc[2][3], xv2, wb.y); fma2(acc[3][3], xv3, wb.y);
    }

#pragma unroll
    for (int i = 0; i < 4; i++) {
        int node = base + ng + 32 * i;
        if (node >= n) continue;
        float4* oh = reinterpret_cast<float4*>(g_h2 + node * OUTC + cg * 4);
        oh[0] = make_float4(unpack_sum(acc[i][0]), unpack_sum(acc[i][1]),
                            unpack_sum(acc[i][2]), unpack_sum(acc[i][3]));
    }
}

// ---------------- layer-2 aggregation: warp per dst node ----------------
// out[d] = dd*( sum_s dis[s]*h2[s] + dd*h2[d] ) + b2,  lane holds 1 ch.

__global__ __launch_bounds__(256) void k_agg2(const float* __restrict__ b2,
                                              float* __restrict__ out, int n) {
    int warp = (blockIdx.x * blockDim.x + threadIdx.x) >> 5;
    int lane = threadIdx.x & 31;
    if (warp >= n) return;
    int d = warp;
    float dd = g_dis[d];
    int lo = g_off[d], hi = g_off[d + 1];

    float a0 = dd * g_h2[d * OUTC + lane];
    float a1 = 0.f;

    int j = lo;
    for (; j + 1 < hi; j += 2) {
        int s0 = g_csrc[j];
        int s1 = g_csrc[j + 1];
        float w0 = g_dis[s0];
        float w1 = g_dis[s1];
        a0 += w0 * g_h2[s0 * OUTC + lane];
        a1 += w1 * g_h2[s1 * OUTC + lane];
    }
    if (j < hi) {
        int s0 = g_csrc[j];
        a0 += g_dis[s0] * g_h2[s0 * OUTC + lane];
    }

    out[d * OUTC + lane] = (a0 + a1) * dd + b2[lane];
}

// ---------------- launch ----------------

extern "C" void kernel_launch(void* const* d_in, const int* in_sizes, int n_in,
                              void* d_out, int out_size) {
    const float* x  = (const float*)d_in[0];
    const int*   ei = (const int*)  d_in[1];
    const float* W1 = (const float*)d_in[2];
    const float* b1 = (const float*)d_in[3];
    const float* W2 = (const float*)d_in[4];
    const float* b2 = (const float*)d_in[5];
    float* out = (float*)d_out;

    int N = in_sizes[0] / IN_CH;
    int E = in_sizes[1] / 2;

    const int T = 256;
    k_zero   <<<(N + T - 1) / T, T>>>(N);
    k_count  <<<(E + T - 1) / T, T>>>(ei, E);
    k_scan   <<<1, 1024>>>(N);
    k_scatter<<<(E + T - 1) / T, T>>>(ei, E);

    k_gemm1<<<(N + 63) / 64, 256>>>(x, W1, N);
    k_agg1 <<<(N * 32 + T - 1) / T, T>>>(b1, N);

    k_gemm2<<<(N + 127) / 128, 256>>>(W2, N);
    k_agg2 <<<(N * 32 + T - 1) / T, T>>>(b2, out, N);
}

// round 6
// speedup vs baseline: 1.4324x; 1.4324x over previous
#include <cuda_runtime.h>
#include <cuda_bf16.h>
#include <cuda_fp16.h>

// GCN 2-layer, scatter formulation (R3 structure) + fp16 gather operands:
//   agg1 = dis^2*(X@W1) + b1  (+ edge msgs via red.add)
//   out  = dis^2*(relu(agg1)@W2) + b2 (+ edge msgs via red.add)
// Neighbor messages gather fp16 copies (h1h/h2h); accumulation stays fp32.

#define NMAX   100000
#define EMAX   1600000
#define IN_CH  128
#define HID    64
#define OUTC   32

typedef unsigned long long ull;

__device__ int    g_deg[NMAX];
__device__ float  g_dis[NMAX];
__device__ float  g_agg1[NMAX * HID];      // fp32 accumulator, layer 1
__device__ __half g_h1h[NMAX * HID];       // fp16 copy of x@W1 (gather operand)
__device__ __half g_h2h[NMAX * OUTC];      // fp16 copy of relu(agg1)@W2

__device__ __forceinline__ void red_add_v4(float* addr, float4 v) {
    asm volatile("red.global.add.v4.f32 [%0], {%1,%2,%3,%4};"
                 :: "l"(addr), "f"(v.x), "f"(v.y), "f"(v.z), "f"(v.w)
                 : "memory");
}

// packed dual-fp32 FMA
__device__ __forceinline__ void fma2(ull& acc, ull a, ull b) {
    asm("fma.rn.f32x2 %0, %1, %2, %0;" : "+l"(acc) : "l"(a), "l"(b));
}
__device__ __forceinline__ float unpack_sum(ull v) {
    float2 f;
    asm("mov.b64 {%0, %1}, %2;" : "=f"(f.x), "=f"(f.y) : "l"(v));
    return f.x + f.y;
}

// ---------------- degree / normalization ----------------

__global__ void k_deg_init(int n) {
    int i = blockIdx.x * blockDim.x + threadIdx.x;
    if (i < n) g_deg[i] = 1;               // self loop
}

__global__ void k_deg_count(const int* __restrict__ ei, int E) {
    int e = blockIdx.x * blockDim.x + threadIdx.x;
    if (e < E) atomicAdd(&g_deg[ei[E + e]], 1);
}

__global__ void k_dis(int n) {
    int i = blockIdx.x * blockDim.x + threadIdx.x;
    if (i < n) g_dis[i] = rsqrtf((float)g_deg[i]);
}

// ---------------- GEMM1: h1 = x @ W1; agg1 = dis^2*h1 + b1; h1h = fp16(h1)
// 64 nodes x 64 ch / block, 256 thr, f32x2 K-pairing.

#define KC 64

__global__ __launch_bounds__(256) void k_gemm1(const float* __restrict__ x,
                                               const float* __restrict__ W1,
                                               const float* __restrict__ b1,
                                               int n) {
    __shared__ float sx[64 * 66];
    __shared__ float sWp[(KC / 2) * 128];

    int tid = threadIdx.x;
    int base = blockIdx.x * 64;
    int ng = tid & 31;
    int cg = tid >> 5;

    ull acc[2][8];
#pragma unroll
    for (int i = 0; i < 2; i++)
#pragma unroll
        for (int j = 0; j < 8; j++) acc[i][j] = 0ull;

    for (int kc = 0; kc < IN_CH; kc += KC) {
        __syncthreads();
#pragma unroll
        for (int i = 0; i < 16; i++) {
            int idx = tid + 256 * i;
            int k = idx >> 6, c = idx & 63;
            sWp[(k >> 1) * 128 + c * 2 + (k & 1)] = W1[(kc + k) * HID + c];
        }
#pragma unroll
        for (int i = 0; i < 4; i++) {
            int f = tid + 256 * i;
            int node = f >> 4;
            int q = f & 15;
            int gn = base + node;
            float4 v = make_float4(0.f, 0.f, 0.f, 0.f);
            if (gn < n) v = reinterpret_cast<const float4*>(x + gn * IN_CH + kc)[q];
            float* r = sx + node * 66 + 4 * q;
            r[0] = v.x; r[1] = v.y; r[2] = v.z; r[3] = v.w;
        }
        __syncthreads();

#pragma unroll
        for (int k2 = 0; k2 < KC / 2; k2++) {
            ull xv0 = *reinterpret_cast<const ull*>(sx + ng * 66 + 2 * k2);
            ull xv1 = *reinterpret_cast<const ull*>(sx + (ng + 32) * 66 + 2 * k2);
            const ulonglong2* wr =
                reinterpret_cast<const ulonglong2*>(sWp + k2 * 128 + cg * 16);
            ulonglong2 wa = wr[0], wb = wr[1], wc = wr[2], wd = wr[3];
            fma2(acc[0][0], xv0, wa.x); fma2(acc[1][0], xv1, wa.x);
            fma2(acc[0][1], xv0, wa.y); fma2(acc[1][1], xv1, wa.y);
            fma2(acc[0][2], xv0, wb.x); fma2(acc[1][2], xv1, wb.x);
            fma2(acc[0][3], xv0, wb.y); fma2(acc[1][3], xv1, wb.y);
            fma2(acc[0][4], xv0, wc.x); fma2(acc[1][4], xv1, wc.x);
            fma2(acc[0][5], xv0, wc.y); fma2(acc[1][5], xv1, wc.y);
            fma2(acc[0][6], xv0, wd.x); fma2(acc[1][6], xv1, wd.x);
            fma2(acc[0][7], xv0, wd.y); fma2(acc[1][7], xv1, wd.y);
        }
    }

    float4 bb0 = reinterpret_cast<const float4*>(b1 + cg * 8)[0];
    float4 bb1 = reinterpret_cast<const float4*>(b1 + cg * 8)[1];
#pragma unroll
    for (int i = 0; i < 2; i++) {
        int node = base + ng + 32 * i;
        if (node >= n) continue;
        float ds = g_dis[node];
        float w = ds * ds;
        float r0 = unpack_sum(acc[i][0]), r1 = unpack_sum(acc[i][1]);
        float r2 = unpack_sum(acc[i][2]), r3 = unpack_sum(acc[i][3]);
        float r4 = unpack_sum(acc[i][4]), r5 = unpack_sum(acc[i][5]);
        float r6 = unpack_sum(acc[i][6]), r7 = unpack_sum(acc[i][7]);
        float4* oa = reinterpret_cast<float4*>(g_agg1 + node * HID + cg * 8);
        oa[0] = make_float4(r0 * w + bb0.x, r1 * w + bb0.y,
                            r2 * w + bb0.z, r3 * w + bb0.w);
        oa[1] = make_float4(r4 * w + bb1.x, r5 * w + bb1.y,
                            r6 * w + bb1.z, r7 * w + bb1.w);
        __half2* oh = reinterpret_cast<__half2*>(g_h1h + node * HID + cg * 8);
        oh[0] = __floats2half2_rn(r0, r1);
        oh[1] = __floats2half2_rn(r2, r3);
        oh[2] = __floats2half2_rn(r4, r5);
        oh[3] = __floats2half2_rn(r6, r7);
    }
}

// ---------------- layer-1 edge scatter: 8 threads/edge, fp16 gather ------

__global__ void k_edge1(const int* __restrict__ ei, int E) {
    int t = blockIdx.x * blockDim.x + threadIdx.x;
    if (t >= E * 8) return;
    int e = t >> 3, q = t & 7;
    int s = ei[e];
    int d = ei[E + e];
    float w = g_dis[s] * g_dis[d];
    // 8 channels = 4 half2 = 16B
    const __half2* hp = reinterpret_cast<const __half2*>(g_h1h + s * HID + q * 8);
    __half2 p0 = hp[0], p1 = hp[1], p2 = hp[2], p3 = hp[3];
    float2 f0 = __half22float2(p0), f1 = __half22float2(p1);
    float2 f2 = __half22float2(p2), f3 = __half22float2(p3);
    float* dst = g_agg1 + d * HID + q * 8;
    red_add_v4(dst,     make_float4(w * f0.x, w * f0.y, w * f1.x, w * f1.y));
    red_add_v4(dst + 4, make_float4(w * f2.x, w * f2.y, w * f3.x, w * f3.y));
}

// ---------------- GEMM2: h2 = relu(agg1)@W2; out = dis^2*h2 + b2; h2h ----
// 128 nodes x 32 ch / block, 256 thr, f32x2 K-pairing, relu fused at stage.

__global__ __launch_bounds__(256) void k_gemm2(const float* __restrict__ W2,
                                               const float* __restrict__ b2,
                                               float* __restrict__ out, int n) {
    __shared__ float sx[128 * 66];
    __shared__ float sWp[(HID / 2) * 64];

    int tid = threadIdx.x;
    int base = blockIdx.x * 128;
    int ng = tid & 31;
    int cg = tid >> 5;

#pragma unroll
    for (int i = 0; i < 8; i++) {
        int idx = tid + 256 * i;
        int k = idx >> 5, c = idx & 31;
        sWp[(k >> 1) * 64 + c * 2 + (k & 1)] = W2[k * OUTC + c];
    }
#pragma unroll
    for (int i = 0; i < 8; i++) {
        int f = tid + 256 * i;
        int node = f >> 4;
        int q = f & 15;
        int gn = base + node;
        float4 v = make_float4(0.f, 0.f, 0.f, 0.f);
        if (gn < n) {
            v = reinterpret_cast<const float4*>(g_agg1 + gn * HID)[q];
            v.x = fmaxf(v.x, 0.f); v.y = fmaxf(v.y, 0.f);
            v.z = fmaxf(v.z, 0.f); v.w = fmaxf(v.w, 0.f);
        }
        float* r = sx + node * 66 + 4 * q;
        r[0] = v.x; r[1] = v.y; r[2] = v.z; r[3] = v.w;
    }
    __syncthreads();

    ull acc[4][4];
#pragma unroll
    for (int i = 0; i < 4; i++)
#pragma unroll
        for (int j = 0; j < 4; j++) acc[i][j] = 0ull;

#pragma unroll
    for (int k2 = 0; k2 < HID / 2; k2++) {
        ull xv0 = *reinterpret_cast<const ull*>(sx + ng * 66 + 2 * k2);
        ull xv1 = *reinterpret_cast<const ull*>(sx + (ng + 32) * 66 + 2 * k2);
        ull xv2 = *reinterpret_cast<const ull*>(sx + (ng + 64) * 66 + 2 * k2);
        ull xv3 = *reinterpret_cast<const ull*>(sx + (ng + 96) * 66 + 2 * k2);
        const ulonglong2* wr =
            reinterpret_cast<const ulonglong2*>(sWp + k2 * 64 + cg * 8);
        ulonglong2 wa = wr[0], wb = wr[1];
        fma2(acc[0][0], xv0, wa.x); fma2(acc[1][0], xv1, wa.x);
        fma2(acc[2][0], xv2, wa.x); fma2(acc[3][0], xv3, wa.x);
        fma2(acc[0][1], xv0, wa.y); fma2(acc[1][1], xv1, wa.y);
        fma2(acc[2][1], xv2, wa.y); fma2(acc[3][1], xv3, wa.y);
        fma2(acc[0][2], xv0, wb.x); fma2(acc[1][2], xv1, wb.x);
        fma2(acc[2][2], xv2, wb.x); fma2(acc[3][2], xv3, wb.x);
        fma2(acc[0][3], xv0, wb.y); fma2(acc[1][3], xv1, wb.y);
        fma2(acc[2][3], xv2, wb.y); fma2(acc[3][3], xv3, wb.y);
    }

    float4 bb = reinterpret_cast<const float4*>(b2 + cg * 4)[0];
#pragma unroll
    for (int i = 0; i < 4; i++) {
        int node = base + ng + 32 * i;
        if (node >= n) continue;
        float ds = g_dis[node];
        float w = ds * ds;
        float r0 = unpack_sum(acc[i][0]), r1 = unpack_sum(acc[i][1]);
        float r2 = unpack_sum(acc[i][2]), r3 = unpack_sum(acc[i][3]);
        float4* oo = reinterpret_cast<float4*>(out + node * OUTC + cg * 4);
        oo[0] = make_float4(r0 * w + bb.x, r1 * w + bb.y,
                            r2 * w + bb.z, r3 * w + bb.w);
        __half2* oh = reinterpret_cast<__half2*>(g_h2h + node * OUTC + cg * 4);
        oh[0] = __floats2half2_rn(r0, r1);
        oh[1] = __floats2half2_rn(r2, r3);
    }
}

// ---------------- layer-2 edge scatter: 4 threads/edge, fp16 gather ------

__global__ void k_edge2(const int* __restrict__ ei, float* __restrict__ out, int E) {
    int t = blockIdx.x * blockDim.x + threadIdx.x;
    if (t >= E * 4) return;
    int e = t >> 2, q = t & 3;
    int s = ei[e];
    int d = ei[E + e];
    float w = g_dis[s] * g_dis[d];
    const __half2* hp = reinterpret_cast<const __half2*>(g_h2h + s * OUTC + q * 8);
    __half2 p0 = hp[0], p1 = hp[1], p2 = hp[2], p3 = hp[3];
    float2 f0 = __half22float2(p0), f1 = __half22float2(p1);
    float2 f2 = __half22float2(p2), f3 = __half22float2(p3);
    float* dst = out + d * OUTC + q * 8;
    red_add_v4(dst,     make_float4(w * f0.x, w * f0.y, w * f1.x, w * f1.y));
    red_add_v4(dst + 4, make_float4(w * f2.x, w * f2.y, w * f3.x, w * f3.y));
}

// ---------------- launch ----------------

extern "C" void kernel_launch(void* const* d_in, const int* in_sizes, int n_in,
                              void* d_out, int out_size) {
    const float* x  = (const float*)d_in[0];
    const int*   ei = (const int*)  d_in[1];
    const float* W1 = (const float*)d_in[2];
    const float* b1 = (const float*)d_in[3];
    const float* W2 = (const float*)d_in[4];
    const float* b2 = (const float*)d_in[5];
    float* out = (float*)d_out;

    int N = in_sizes[0] / IN_CH;
    int E = in_sizes[1] / 2;

    const int T = 256;
    k_deg_init <<<(N + T - 1) / T, T>>>(N);
    k_deg_count<<<(E + T - 1) / T, T>>>(ei, E);
    k_dis      <<<(N + T - 1) / T, T>>>(N);

    k_gemm1<<<(N + 63) / 64, 256>>>(x, W1, b1, N);
    k_edge1<<<(E * 8 + T - 1) / T, T>>>(ei, E);

    k_gemm2<<<(N + 127) / 128, 256>>>(W2, b2, out, N);
    k_edge2<<<(E * 4 + T - 1) / T, T>>>(ei, out, E);
}

// round 7
// speedup vs baseline: 1.4992x; 1.0466x over previous
#include <cuda_runtime.h>
#include <cuda_bf16.h>
#include <cuda_fp16.h>

// GCN 2-layer, scatter formulation + fp16 gather operands (R3 edge mapping):
//   agg1 = dis^2*(X@W1) + b1  (+ edge msgs via red.add)
//   out  = dis^2*(relu(agg1)@W2) + b2 (+ edge msgs via red.add)
// Neighbor messages gather fp16 copies (h1h/h2h); accumulation stays fp32.

#define NMAX   100000
#define EMAX   1600000
#define IN_CH  128
#define HID    64
#define OUTC   32

typedef unsigned long long ull;

__device__ int    g_deg[NMAX];
__device__ float  g_dis[NMAX];
__device__ float  g_agg1[NMAX * HID];      // fp32 accumulator, layer 1
__device__ __half g_h1h[NMAX * HID];       // fp16 copy of x@W1 (gather operand)
__device__ __half g_h2h[NMAX * OUTC];      // fp16 copy of relu(agg1)@W2

__device__ __forceinline__ void red_add_v4(float* addr, float4 v) {
    asm volatile("red.global.add.v4.f32 [%0], {%1,%2,%3,%4};"
                 :: "l"(addr), "f"(v.x), "f"(v.y), "f"(v.z), "f"(v.w)
                 : "memory");
}

// packed dual-fp32 FMA
__device__ __forceinline__ void fma2(ull& acc, ull a, ull b) {
    asm("fma.rn.f32x2 %0, %1, %2, %0;" : "+l"(acc) : "l"(a), "l"(b));
}
__device__ __forceinline__ float unpack_sum(ull v) {
    float2 f;
    asm("mov.b64 {%0, %1}, %2;" : "=f"(f.x), "=f"(f.y) : "l"(v));
    return f.x + f.y;
}

// ---------------- degree / normalization ----------------

__global__ void k_deg_init(int n) {
    int i = blockIdx.x * blockDim.x + threadIdx.x;
    if (i < n) g_deg[i] = 1;               // self loop
}

__global__ void k_deg_count(const int* __restrict__ ei, int E) {
    int e = blockIdx.x * blockDim.x + threadIdx.x;
    if (e < E) atomicAdd(&g_deg[ei[E + e]], 1);
}

__global__ void k_dis(int n) {
    int i = blockIdx.x * blockDim.x + threadIdx.x;
    if (i < n) g_dis[i] = rsqrtf((float)g_deg[i]);
}

// ---------------- GEMM1: h1 = x@W1; agg1 = dis^2*h1 + b1; h1h = fp16(h1) --
// Tile: 128 nodes x 64 ch / block, 256 thr, 4 nodes x 8 ch per thread.
// K chunked by 32; f32x2 K-pairing. x tile k2-major float2, row stride 132
// (conflict-free LDS.64); W k-pair interleaved, warp-broadcast LDS.128.

#define KC1 32

__global__ __launch_bounds__(256) void k_gemm1(const float* __restrict__ x,
                                               const float* __restrict__ W1,
                                               const float* __restrict__ b1,
                                               int n) {
    __shared__ float2 sxT[(KC1 / 2) * 132];     // 16 rows x 132 = 16.9 KB
    __shared__ float  sWp[(KC1 / 2) * 128];     // 16 k2 x 64 ch x 2 = 8 KB

    int tid = threadIdx.x;
    int base = blockIdx.x * 128;
    int ng = tid & 31;                          // nodes ng + 32*i
    int cg = tid >> 5;                          // ch 8*cg .. 8*cg+7

    ull acc[4][8];
#pragma unroll
    for (int i = 0; i < 4; i++)
#pragma unroll
        for (int j = 0; j < 8; j++) acc[i][j] = 0ull;

    for (int kc = 0; kc < IN_CH; kc += KC1) {
        __syncthreads();
        // W chunk: KC1 x 64 = 2048 floats, k-pair interleaved
#pragma unroll
        for (int i = 0; i < (KC1 * HID) / 256; i++) {
            int idx = tid + 256 * i;
            int k = idx >> 6, c = idx & 63;
            sWp[(k >> 1) * 128 + c * 2 + (k & 1)] = W1[(kc + k) * HID + c];
        }
        // x chunk: 128 nodes x KC1, stored k2-major as float2
#pragma unroll
        for (int i = 0; i < 4; i++) {
            int f = tid + 256 * i;              // 0..1023
            int node = f >> 3;                  // 0..127
            int q = f & 7;                      // float4 index within chunk
            int gn = base + node;
            float4 v = make_float4(0.f, 0.f, 0.f, 0.f);
            if (gn < n) v = reinterpret_cast<const float4*>(x + gn * IN_CH + kc)[q];
            sxT[(2 * q + 0) * 132 + node] = make_float2(v.x, v.y);
            sxT[(2 * q + 1) * 132 + node] = make_float2(v.z, v.w);
        }
        __syncthreads();

#pragma unroll
        for (int k2 = 0; k2 < KC1 / 2; k2++) {
            const float2* xr = sxT + k2 * 132 + ng;
            ull xv0 = *reinterpret_cast<const ull*>(xr);
            ull xv1 = *reinterpret_cast<const ull*>(xr + 32);
            ull xv2 = *reinterpret_cast<const ull*>(xr + 64);
            ull xv3 = *reinterpret_cast<const ull*>(xr + 96);
            const ulonglong2* wr =
                reinterpret_cast<const ulonglong2*>(sWp + k2 * 128 + cg * 16);
            ulonglong2 wa = wr[0], wb = wr[1], wc = wr[2], wd = wr[3];
            fma2(acc[0][0], xv0, wa.x); fma2(acc[1][0], xv1, wa.x);
            fma2(acc[2][0], xv2, wa.x); fma2(acc[3][0], xv3, wa.x);
            fma2(acc[0][1], xv0, wa.y); fma2(acc[1][1], xv1, wa.y);
            fma2(acc[2][1], xv2, wa.y); fma2(acc[3][1], xv3, wa.y);
            fma2(acc[0][2], xv0, wb.x); fma2(acc[1][2], xv1, wb.x);
            fma2(acc[2][2], xv2, wb.x); fma2(acc[3][2], xv3, wb.x);
            fma2(acc[0][3], xv0, wb.y); fma2(acc[1][3], xv1, wb.y);
            fma2(acc[2][3], xv2, wb.y); fma2(acc[3][3], xv3, wb.y);
            fma2(acc[0][4], xv0, wc.x); fma2(acc[1][4], xv1, wc.x);
            fma2(acc[2][4], xv2, wc.x); fma2(acc[3][4], xv3, wc.x);
            fma2(acc[0][5], xv0, wc.y); fma2(acc[1][5], xv1, wc.y);
            fma2(acc[2][5], xv2, wc.y); fma2(acc[3][5], xv3, wc.y);
            fma2(acc[0][6], xv0, wd.x); fma2(acc[1][6], xv1, wd.x);
            fma2(acc[2][6], xv2, wd.x); fma2(acc[3][6], xv3, wd.x);
            fma2(acc[0][7], xv0, wd.y); fma2(acc[1][7], xv1, wd.y);
            fma2(acc[2][7], xv2, wd.y); fma2(acc[3][7], xv3, wd.y);
        }
    }

    float4 bb0 = reinterpret_cast<const float4*>(b1 + cg * 8)[0];
    float4 bb1 = reinterpret_cast<const float4*>(b1 + cg * 8)[1];
#pragma unroll
    for (int i = 0; i < 4; i++) {
        int node = base + ng + 32 * i;
        if (node >= n) continue;
        float ds = g_dis[node];
        float w = ds * ds;
        float r0 = unpack_sum(acc[i][0]), r1 = unpack_sum(acc[i][1]);
        float r2 = unpack_sum(acc[i][2]), r3 = unpack_sum(acc[i][3]);
        float r4 = unpack_sum(acc[i][4]), r5 = unpack_sum(acc[i][5]);
        float r6 = unpack_sum(acc[i][6]), r7 = unpack_sum(acc[i][7]);
        float4* oa = reinterpret_cast<float4*>(g_agg1 + node * HID + cg * 8);
        oa[0] = make_float4(r0 * w + bb0.x, r1 * w + bb0.y,
                            r2 * w + bb0.z, r3 * w + bb0.w);
        oa[1] = make_float4(r4 * w + bb1.x, r5 * w + bb1.y,
                            r6 * w + bb1.z, r7 * w + bb1.w);
        __half2* oh = reinterpret_cast<__half2*>(g_h1h + node * HID + cg * 8);
        oh[0] = __floats2half2_rn(r0, r1);
        oh[1] = __floats2half2_rn(r2, r3);
        oh[2] = __floats2half2_rn(r4, r5);
        oh[3] = __floats2half2_rn(r6, r7);
    }
}

// ---------------- layer-1 edge scatter: 16 threads/edge, fp16 gather -----

__global__ void k_edge1(const int* __restrict__ ei, int E) {
    int t = blockIdx.x * blockDim.x + threadIdx.x;
    if (t >= E * 16) return;
    int e = t >> 4, q = t & 15;
    int s = ei[e];
    int d = ei[E + e];
    float w = g_dis[s] * g_dis[d];
    // 4 channels = 2 half2 = 8B
    const __half2* hp = reinterpret_cast<const __half2*>(g_h1h + s * HID + q * 4);
    __half2 p0 = hp[0], p1 = hp[1];
    float2 f0 = __half22float2(p0), f1 = __half22float2(p1);
    red_add_v4(g_agg1 + d * HID + q * 4,
               make_float4(w * f0.x, w * f0.y, w * f1.x, w * f1.y));
}

// ---------------- GEMM2: h2 = relu(agg1)@W2; out = dis^2*h2 + b2; h2h ----
// 128 nodes x 32 ch / block, 256 thr, f32x2 K-pairing, relu fused at stage.

__global__ __launch_bounds__(256) void k_gemm2(const float* __restrict__ W2,
                                               const float* __restrict__ b2,
                                               float* __restrict__ out, int n) {
    __shared__ float sx[128 * 66];
    __shared__ float sWp[(HID / 2) * 64];

    int tid = threadIdx.x;
    int base = blockIdx.x * 128;
    int ng = tid & 31;
    int cg = tid >> 5;

#pragma unroll
    for (int i = 0; i < 8; i++) {
        int idx = tid + 256 * i;
        int k = idx >> 5, c = idx & 31;
        sWp[(k >> 1) * 64 + c * 2 + (k & 1)] = W2[k * OUTC + c];
    }
#pragma unroll
    for (int i = 0; i < 8; i++) {
        int f = tid + 256 * i;
        int node = f >> 4;
        int q = f & 15;
        int gn = base + node;
        float4 v = make_float4(0.f, 0.f, 0.f, 0.f);
        if (gn < n) {
            v = reinterpret_cast<const float4*>(g_agg1 + gn * HID)[q];
            v.x = fmaxf(v.x, 0.f); v.y = fmaxf(v.y, 0.f);
            v.z = fmaxf(v.z, 0.f); v.w = fmaxf(v.w, 0.f);
        }
        float* r = sx + node * 66 + 4 * q;
        r[0] = v.x; r[1] = v.y; r[2] = v.z; r[3] = v.w;
    }
    __syncthreads();

    ull acc[4][4];
#pragma unroll
    for (int i = 0; i < 4; i++)
#pragma unroll
        for (int j = 0; j < 4; j++) acc[i][j] = 0ull;

#pragma unroll
    for (int k2 = 0; k2 < HID / 2; k2++) {
        ull xv0 = *reinterpret_cast<const ull*>(sx + ng * 66 + 2 * k2);
        ull xv1 = *reinterpret_cast<const ull*>(sx + (ng + 32) * 66 + 2 * k2);
        ull xv2 = *reinterpret_cast<const ull*>(sx + (ng + 64) * 66 + 2 * k2);
        ull xv3 = *reinterpret_cast<const ull*>(sx + (ng + 96) * 66 + 2 * k2);
        const ulonglong2* wr =
            reinterpret_cast<const ulonglong2*>(sWp + k2 * 64 + cg * 8);
        ulonglong2 wa = wr[0], wb = wr[1];
        fma2(acc[0][0], xv0, wa.x); fma2(acc[1][0], xv1, wa.x);
        fma2(acc[2][0], xv2, wa.x); fma2(acc[3][0], xv3, wa.x);
        fma2(acc[0][1], xv0, wa.y); fma2(acc[1][1], xv1, wa.y);
        fma2(acc[2][1], xv2, wa.y); fma2(acc[3][1], xv3, wa.y);
        fma2(acc[0][2], xv0, wb.x); fma2(acc[1][2], xv1, wb.x);
        fma2(acc[2][2], xv2, wb.x); fma2(acc[3][2], xv3, wb.x);
        fma2(acc[0][3], xv0, wb.y); fma2(acc[1][3], xv1, wb.y);
        fma2(acc[2][3], xv2, wb.y); fma2(acc[3][3], xv3, wb.y);
    }

    float4 bb = reinterpret_cast<const float4*>(b2 + cg * 4)[0];
#pragma unroll
    for (int i = 0; i < 4; i++) {
        int node = base + ng + 32 * i;
        if (node >= n) continue;
        float ds = g_dis[node];
        float w = ds * ds;
        float r0 = unpack_sum(acc[i][0]), r1 = unpack_sum(acc[i][1]);
        float r2 = unpack_sum(acc[i][2]), r3 = unpack_sum(acc[i][3]);
        float4* oo = reinterpret_cast<float4*>(out + node * OUTC + cg * 4);
        oo[0] = make_float4(r0 * w + bb.x, r1 * w + bb.y,
                            r2 * w + bb.z, r3 * w + bb.w);
        __half2* oh = reinterpret_cast<__half2*>(g_h2h + node * OUTC + cg * 4);
        oh[0] = __floats2half2_rn(r0, r1);
        oh[1] = __floats2half2_rn(r2, r3);
    }
}

// ---------------- layer-2 edge scatter: 8 threads/edge, fp16 gather ------

__global__ void k_edge2(const int* __restrict__ ei, float* __restrict__ out, int E) {
    int t = blockIdx.x * blockDim.x + threadIdx.x;
    if (t >= E * 8) return;
    int e = t >> 3, q = t & 7;
    int s = ei[e];
    int d = ei[E + e];
    float w = g_dis[s] * g_dis[d];
    const __half2* hp = reinterpret_cast<const __half2*>(g_h2h + s * OUTC + q * 4);
    __half2 p0 = hp[0], p1 = hp[1];
    float2 f0 = __half22float2(p0), f1 = __half22float2(p1);
    red_add_v4(out + d * OUTC + q * 4,
               make_float4(w * f0.x, w * f0.y, w * f1.x, w * f1.y));
}

// ---------------- launch ----------------

extern "C" void kernel_launch(void* const* d_in, const int* in_sizes, int n_in,
                              void* d_out, int out_size) {
    const float* x  = (const float*)d_in[0];
    const int*   ei = (const int*)  d_in[1];
    const float* W1 = (const float*)d_in[2];
    const float* b1 = (const float*)d_in[3];
    const float* W2 = (const float*)d_in[4];
    const float* b2 = (const float*)d_in[5];
    float* out = (float*)d_out;

    int N = in_sizes[0] / IN_CH;
    int E = in_sizes[1] / 2;

    const int T = 256;
    k_deg_init <<<(N + T - 1) / T, T>>>(N);
    k_deg_count<<<(E + T - 1) / T, T>>>(ei, E);
    k_dis      <<<(N + T - 1) / T, T>>>(N);

    k_gemm1<<<(N + 127) / 128, 256>>>(x, W1, b1, N);
    k_edge1<<<(E * 16 + T - 1) / T, T>>>(ei, E);

    k_gemm2<<<(N + 127) / 128, 256>>>(W2, b2, out, N);
    k_edge2<<<(E * 8 + T - 1) / T, T>>>(ei, out, E);
}

// round 8
// speedup vs baseline: 1.6112x; 1.0747x over previous
#include <cuda_runtime.h>
#include <cuda_bf16.h>
#include <cuda_fp16.h>

// GCN 2-layer, scatter formulation + fp16 gather operands:
//   agg1 = dis^2*(X@W1) + b1  (+ edge msgs via red.add)
//   out  = dis^2*(relu(agg1)@W2) + b2 (+ edge msgs via red.add)
// Neighbor messages gather fp16 copies (h1h/h2h); accumulation stays fp32.

#define NMAX   100000
#define EMAX   1600000
#define IN_CH  128
#define HID    64
#define OUTC   32

typedef unsigned long long ull;

__device__ int    g_deg[NMAX];
__device__ float  g_dis[NMAX];
__device__ float  g_agg1[NMAX * HID];      // fp32 accumulator, layer 1
__device__ __half g_h1h[NMAX * HID];       // fp16 copy of x@W1 (gather operand)
__device__ __half g_h2h[NMAX * OUTC];      // fp16 copy of relu(agg1)@W2

__device__ __forceinline__ void red_add_v4(float* addr, float4 v) {
    asm volatile("red.global.add.v4.f32 [%0], {%1,%2,%3,%4};"
                 :: "l"(addr), "f"(v.x), "f"(v.y), "f"(v.z), "f"(v.w)
                 : "memory");
}

// packed dual-fp32 FMA
__device__ __forceinline__ void fma2(ull& acc, ull a, ull b) {
    asm("fma.rn.f32x2 %0, %1, %2, %0;" : "+l"(acc) : "l"(a), "l"(b));
}
__device__ __forceinline__ float unpack_sum(ull v) {
    float2 f;
    asm("mov.b64 {%0, %1}, %2;" : "=f"(f.x), "=f"(f.y) : "l"(v));
    return f.x + f.y;
}

// ---------------- degree / normalization ----------------

__global__ void k_deg_init(int n) {
    int i = blockIdx.x * blockDim.x + threadIdx.x;
    if (i < n) g_deg[i] = 1;               // self loop
}

__global__ void k_deg_count(const int* __restrict__ ei, int E) {
    int e = blockIdx.x * blockDim.x + threadIdx.x;
    if (e < E) atomicAdd(&g_deg[ei[E + e]], 1);
}

__global__ void k_dis(int n) {
    int i = blockIdx.x * blockDim.x + threadIdx.x;
    if (i < n) g_dis[i] = rsqrtf((float)g_deg[i]);
}

// ---------------- GEMM1: h1 = x@W1; agg1 = dis^2*h1 + b1; h1h = fp16(h1) --
// Tile: 64 nodes x 64 ch / block, 256 thr, 2 nodes x 8 ch per thread.
// K chunked by 64; f32x2 K-pairing. sx node-major stride 66 (conflict-free
// LDS.64); sWp k-pair interleaved, warp-broadcast LDS.128. (R3/R6 config.)

#define KC 64

__global__ __launch_bounds__(256) void k_gemm1(const float* __restrict__ x,
                                               const float* __restrict__ W1,
                                               const float* __restrict__ b1,
                                               int n) {
    __shared__ float sx[64 * 66];            // 16.5 KB
    __shared__ float sWp[(KC / 2) * 128];    // 16 KB

    int tid = threadIdx.x;
    int base = blockIdx.x * 64;
    int ng = tid & 31;                       // nodes ng, ng+32
    int cg = tid >> 5;                       // ch 8*cg .. 8*cg+7

    ull acc[2][8];
#pragma unroll
    for (int i = 0; i < 2; i++)
#pragma unroll
        for (int j = 0; j < 8; j++) acc[i][j] = 0ull;

    for (int kc = 0; kc < IN_CH; kc += KC) {
        __syncthreads();
#pragma unroll
        for (int i = 0; i < 16; i++) {
            int idx = tid + 256 * i;
            int k = idx >> 6, c = idx & 63;
            sWp[(k >> 1) * 128 + c * 2 + (k & 1)] = W1[(kc + k) * HID + c];
        }
#pragma unroll
        for (int i = 0; i < 4; i++) {
            int f = tid + 256 * i;           // 0..1023
            int node = f >> 4;
            int q = f & 15;
            int gn = base + node;
            float4 v = make_float4(0.f, 0.f, 0.f, 0.f);
            if (gn < n) v = reinterpret_cast<const float4*>(x + gn * IN_CH + kc)[q];
            float* r = sx + node * 66 + 4 * q;
            r[0] = v.x; r[1] = v.y; r[2] = v.z; r[3] = v.w;
        }
        __syncthreads();

#pragma unroll
        for (int k2 = 0; k2 < KC / 2; k2++) {
            ull xv0 = *reinterpret_cast<const ull*>(sx + ng * 66 + 2 * k2);
            ull xv1 = *reinterpret_cast<const ull*>(sx + (ng + 32) * 66 + 2 * k2);
            const ulonglong2* wr =
                reinterpret_cast<const ulonglong2*>(sWp + k2 * 128 + cg * 16);
            ulonglong2 wa = wr[0], wb = wr[1], wc = wr[2], wd = wr[3];
            fma2(acc[0][0], xv0, wa.x); fma2(acc[1][0], xv1, wa.x);
            fma2(acc[0][1], xv0, wa.y); fma2(acc[1][1], xv1, wa.y);
            fma2(acc[0][2], xv0, wb.x); fma2(acc[1][2], xv1, wb.x);
            fma2(acc[0][3], xv0, wb.y); fma2(acc[1][3], xv1, wb.y);
            fma2(acc[0][4], xv0, wc.x); fma2(acc[1][4], xv1, wc.x);
            fma2(acc[0][5], xv0, wc.y); fma2(acc[1][5], xv1, wc.y);
            fma2(acc[0][6], xv0, wd.x); fma2(acc[1][6], xv1, wd.x);
            fma2(acc[0][7], xv0, wd.y); fma2(acc[1][7], xv1, wd.y);
        }
    }

    float4 bb0 = reinterpret_cast<const float4*>(b1 + cg * 8)[0];
    float4 bb1 = reinterpret_cast<const float4*>(b1 + cg * 8)[1];
#pragma unroll
    for (int i = 0; i < 2; i++) {
        int node = base + ng + 32 * i;
        if (node >= n) continue;
        float ds = g_dis[node];
        float w = ds * ds;
        float r0 = unpack_sum(acc[i][0]), r1 = unpack_sum(acc[i][1]);
        float r2 = unpack_sum(acc[i][2]), r3 = unpack_sum(acc[i][3]);
        float r4 = unpack_sum(acc[i][4]), r5 = unpack_sum(acc[i][5]);
        float r6 = unpack_sum(acc[i][6]), r7 = unpack_sum(acc[i][7]);
        float4* oa = reinterpret_cast<float4*>(g_agg1 + node * HID + cg * 8);
        oa[0] = make_float4(r0 * w + bb0.x, r1 * w + bb0.y,
                            r2 * w + bb0.z, r3 * w + bb0.w);
        oa[1] = make_float4(r4 * w + bb1.x, r5 * w + bb1.y,
                            r6 * w + bb1.z, r7 * w + bb1.w);
        __half2* oh = reinterpret_cast<__half2*>(g_h1h + node * HID + cg * 8);
        oh[0] = __floats2half2_rn(r0, r1);
        oh[1] = __floats2half2_rn(r2, r3);
        oh[2] = __floats2half2_rn(r4, r5);
        oh[3] = __floats2half2_rn(r6, r7);
    }
}

// ---------------- layer-1 edge scatter: 16 threads/edge, fp16 gather -----

__global__ void k_edge1(const int* __restrict__ ei, int E) {
    int t = blockIdx.x * blockDim.x + threadIdx.x;
    if (t >= E * 16) return;
    int e = t >> 4, q = t & 15;
    int s = ei[e];
    int d = ei[E + e];
    float w = g_dis[s] * g_dis[d];
    // 4 channels = 2 half2 = 8B
    const __half2* hp = reinterpret_cast<const __half2*>(g_h1h + s * HID + q * 4);
    __half2 p0 = hp[0], p1 = hp[1];
    float2 f0 = __half22float2(p0), f1 = __half22float2(p1);
    red_add_v4(g_agg1 + d * HID + q * 4,
               make_float4(w * f0.x, w * f0.y, w * f1.x, w * f1.y));
}

// ---------------- GEMM2: h2 = relu(agg1)@W2; out = dis^2*h2 + b2; h2h ----
// 128 nodes x 32 ch / block, 256 thr, f32x2 K-pairing, relu fused at stage.

__global__ __launch_bounds__(256) void k_gemm2(const float* __restrict__ W2,
                                               const float* __restrict__ b2,
                                               float* __restrict__ out, int n) {
    __shared__ float sx[128 * 66];
    __shared__ float sWp[(HID / 2) * 64];

    int tid = threadIdx.x;
    int base = blockIdx.x * 128;
    int ng = tid & 31;
    int cg = tid >> 5;

#pragma unroll
    for (int i = 0; i < 8; i++) {
        int idx = tid + 256 * i;
        int k = idx >> 5, c = idx & 31;
        sWp[(k >> 1) * 64 + c * 2 + (k & 1)] = W2[k * OUTC + c];
    }
#pragma unroll
    for (int i = 0; i < 8; i++) {
        int f = tid + 256 * i;
        int node = f >> 4;
        int q = f & 15;
        int gn = base + node;
        float4 v = make_float4(0.f, 0.f, 0.f, 0.f);
        if (gn < n) {
            v = reinterpret_cast<const float4*>(g_agg1 + gn * HID)[q];
            v.x = fmaxf(v.x, 0.f); v.y = fmaxf(v.y, 0.f);
            v.z = fmaxf(v.z, 0.f); v.w = fmaxf(v.w, 0.f);
        }
        float* r = sx + node * 66 + 4 * q;
        r[0] = v.x; r[1] = v.y; r[2] = v.z; r[3] = v.w;
    }
    __syncthreads();

    ull acc[4][4];
#pragma unroll
    for (int i = 0; i < 4; i++)
#pragma unroll
        for (int j = 0; j < 4; j++) acc[i][j] = 0ull;

#pragma unroll
    for (int k2 = 0; k2 < HID / 2; k2++) {
        ull xv0 = *reinterpret_cast<const ull*>(sx + ng * 66 + 2 * k2);
        ull xv1 = *reinterpret_cast<const ull*>(sx + (ng + 32) * 66 + 2 * k2);
        ull xv2 = *reinterpret_cast<const ull*>(sx + (ng + 64) * 66 + 2 * k2);
        ull xv3 = *reinterpret_cast<const ull*>(sx + (ng + 96) * 66 + 2 * k2);
        const ulonglong2* wr =
            reinterpret_cast<const ulonglong2*>(sWp + k2 * 64 + cg * 8);
        ulonglong2 wa = wr[0], wb = wr[1];
        fma2(acc[0][0], xv0, wa.x); fma2(acc[1][0], xv1, wa.x);
        fma2(acc[2][0], xv2, wa.x); fma2(acc[3][0], xv3, wa.x);
        fma2(acc[0][1], xv0, wa.y); fma2(acc[1][1], xv1, wa.y);
        fma2(acc[2][1], xv2, wa.y); fma2(acc[3][1], xv3, wa.y);
        fma2(acc[0][2], xv0, wb.x); fma2(acc[1][2], xv1, wb.x);
        fma2(acc[2][2], xv2, wb.x); fma2(acc[3][2], xv3, wb.x);
        fma2(acc[0][3], xv0, wb.y); fma2(acc[1][3], xv1, wb.y);
        fma2(acc[2][3], xv2, wb.y); fma2(acc[3][3], xv3, wb.y);
    }

    float4 bb = reinterpret_cast<const float4*>(b2 + cg * 4)[0];
#pragma unroll
    for (int i = 0; i < 4; i++) {
        int node = base + ng + 32 * i;
        if (node >= n) continue;
        float ds = g_dis[node];
        float w = ds * ds;
        float r0 = unpack_sum(acc[i][0]), r1 = unpack_sum(acc[i][1]);
        float r2 = unpack_sum(acc[i][2]), r3 = unpack_sum(acc[i][3]);
        float4* oo = reinterpret_cast<float4*>(out + node * OUTC + cg * 4);
        oo[0] = make_float4(r0 * w + bb.x, r1 * w + bb.y,
                            r2 * w + bb.z, r3 * w + bb.w);
        __half2* oh = reinterpret_cast<__half2*>(g_h2h + node * OUTC + cg * 4);
        oh[0] = __floats2half2_rn(r0, r1);
        oh[1] = __floats2half2_rn(r2, r3);
    }
}

// ---------------- layer-2 edge scatter: 8 threads/edge, fp16 gather ------

__global__ void k_edge2(const int* __restrict__ ei, float* __restrict__ out, int E) {
    int t = blockIdx.x * blockDim.x + threadIdx.x;
    if (t >= E * 8) return;
    int e = t >> 3, q = t & 7;
    int s = ei[e];
    int d = ei[E + e];
    float w = g_dis[s] * g_dis[d];
    const __half2* hp = reinterpret_cast<const __half2*>(g_h2h + s * OUTC + q * 4);
    __half2 p0 = hp[0], p1 = hp[1];
    float2 f0 = __half22float2(p0), f1 = __half22float2(p1);
    red_add_v4(out + d * OUTC + q * 4,
               make_float4(w * f0.x, w * f0.y, w * f1.x, w * f1.y));
}

// ---------------- launch ----------------

extern "C" void kernel_launch(void* const* d_in, const int* in_sizes, int n_in,
                              void* d_out, int out_size) {
    const float* x  = (const float*)d_in[0];
    const int*   ei = (const int*)  d_in[1];
    const float* W1 = (const float*)d_in[2];
    const float* b1 = (const float*)d_in[3];
    const float* W2 = (const float*)d_in[4];
    const float* b2 = (const float*)d_in[5];
    float* out = (float*)d_out;

    int N = in_sizes[0] / IN_CH;
    int E = in_sizes[1] / 2;

    const int T = 256;
    k_deg_init <<<(N + T - 1) / T, T>>>(N);
    k_deg_count<<<(E + T - 1) / T, T>>>(ei, E);
    k_dis      <<<(N + T - 1) / T, T>>>(N);

    k_gemm1<<<(N + 63) / 64, 256>>>(x, W1, b1, N);
    k_edge1<<<(E * 16 + T - 1) / T, T>>>(ei, E);

    k_gemm2<<<(N + 127) / 128, 256>>>(W2, b2, out, N);
    k_edge2<<<(E * 8 + T - 1) / T, T>>>(ei, out, E);
}

// round 9
// speedup vs baseline: 1.7675x; 1.0970x over previous
#include <cuda_runtime.h>
#include <cuda_bf16.h>
#include <cuda_fp16.h>
#include <cstdint>

// GCN 2-layer, scatter formulation + fp16 gather operands.
// GEMM1 now uses tf32 mma.sync tensor-core path (fragment-packed smem).

#define NMAX   100000
#define EMAX   1600000
#define IN_CH  128
#define HID    64
#define OUTC   32

typedef unsigned long long ull;

__device__ int    g_deg[NMAX];
__device__ float  g_dis[NMAX];
__device__ float  g_agg1[NMAX * HID];      // fp32 accumulator, layer 1
__device__ __half g_h1h[NMAX * HID];       // fp16 copy of x@W1 (gather operand)
__device__ __half g_h2h[NMAX * OUTC];      // fp16 copy of relu(agg1)@W2

__device__ __forceinline__ void red_add_v4(float* addr, float4 v) {
    asm volatile("red.global.add.v4.f32 [%0], {%1,%2,%3,%4};"
                 :: "l"(addr), "f"(v.x), "f"(v.y), "f"(v.z), "f"(v.w)
                 : "memory");
}

// packed dual-fp32 FMA (gemm2)
__device__ __forceinline__ void fma2(ull& acc, ull a, ull b) {
    asm("fma.rn.f32x2 %0, %1, %2, %0;" : "+l"(acc) : "l"(a), "l"(b));
}
__device__ __forceinline__ float unpack_sum(ull v) {
    float2 f;
    asm("mov.b64 {%0, %1}, %2;" : "=f"(f.x), "=f"(f.y) : "l"(v));
    return f.x + f.y;
}

__device__ __forceinline__ uint32_t to_tf32(float f) {
    uint32_t r;
    asm("cvt.rna.tf32.f32 %0, %1;" : "=r"(r) : "f"(f));
    return r;
}

__device__ __forceinline__ void mma_tf32(float* d, const uint32_t* a, const uint32_t* b) {
    asm("mma.sync.aligned.m16n8k8.row.col.f32.tf32.tf32.f32 "
        "{%0,%1,%2,%3}, {%4,%5,%6,%7}, {%8,%9}, {%0,%1,%2,%3};"
        : "+f"(d[0]), "+f"(d[1]), "+f"(d[2]), "+f"(d[3])
        : "r"(a[0]), "r"(a[1]), "r"(a[2]), "r"(a[3]), "r"(b[0]), "r"(b[1]));
}

// ---------------- degree / normalization ----------------

__global__ void k_deg_init(int n) {
    int i = blockIdx.x * blockDim.x + threadIdx.x;
    if (i < n) g_deg[i] = 1;               // self loop
}

__global__ void k_deg_count(const int* __restrict__ ei, int E) {
    int e = blockIdx.x * blockDim.x + threadIdx.x;
    if (e < E) atomicAdd(&g_deg[ei[E + e]], 1);
}

__global__ void k_dis(int n) {
    int i = blockIdx.x * blockDim.x + threadIdx.x;
    if (i < n) g_dis[i] = rsqrtf((float)g_deg[i]);
}

// ---------------- GEMM1 (tf32 tensor core) -------------------------------
// h1 = x@W1; agg1 = dis^2*h1 + b1; h1h = fp16(h1)
// CTA: 128 nodes (M) x 64 ch (N), K=128 chunked by 32. 8 warps in 4(M)x2(N);
// warp tile 32x32 = 2x4 m16n8k8 frags. smem tiles are fragment-packed:
//   sA[m_tile(8)][kstep(4)][lane(32)][4]  (A row-major frag, LDS.128/lane)
//   sB[n_tile(8)][kstep(4)][lane(32)][2]  (B col-major frag, LDS.64/lane)

#define KCT 32

__global__ __launch_bounds__(256) void k_gemm1(const float* __restrict__ x,
                                               const float* __restrict__ W1,
                                               const float* __restrict__ b1,
                                               int n) {
    __shared__ uint32_t sA[8 * 4 * 32 * 4];   // 16 KB
    __shared__ uint32_t sB[8 * 4 * 32 * 2];   // 8 KB

    int tid = threadIdx.x;
    int lane = tid & 31;
    int wid = tid >> 5;
    int warp_m = wid & 3;                     // 0..3 -> m offset 32*warp_m
    int warp_n = wid >> 2;                    // 0..1 -> n offset 32*warp_n
    int base = blockIdx.x * 128;

    float acc[2][4][4];
#pragma unroll
    for (int fm = 0; fm < 2; fm++)
#pragma unroll
        for (int fn = 0; fn < 4; fn++)
#pragma unroll
            for (int r = 0; r < 4; r++) acc[fm][fn][r] = 0.f;

    for (int kc = 0; kc < IN_CH; kc += KCT) {
        __syncthreads();
        // stage A: x[base..base+128)[kc..kc+32), fragment-packed
#pragma unroll
        for (int i = 0; i < 4; i++) {
            int f = tid + 256 * i;            // 0..1023
            int node = f >> 3;                // 0..127
            int q = f & 7;                    // float4 idx -> k = 4q..4q+3
            int gn = base + node;
            float4 v = make_float4(0.f, 0.f, 0.f, 0.f);
            if (gn < n) v = reinterpret_cast<const float4*>(x + gn * IN_CH + kc)[q];
            float vv[4] = {v.x, v.y, v.z, v.w};
            int mt = node >> 4, mm = node & 15;
#pragma unroll
            for (int j = 0; j < 4; j++) {
                int k = 4 * q + j;
                int kstep = k >> 3, kk = k & 7;
                int lt = ((mm & 7) << 2) | (kk & 3);
                int idx = (mm >> 3) | ((kk >> 2) << 1);
                sA[(((mt << 2) | kstep) << 7) + (lt << 2) + idx] = to_tf32(vv[j]);
            }
        }
        // stage B: W1[kc..kc+32)[0..64), fragment-packed (col-major frag)
#pragma unroll
        for (int i = 0; i < 2; i++) {
            int f = tid + 256 * i;            // 0..511
            int kr = f >> 4;                  // 0..31
            int qc = f & 15;                  // float4 idx -> c = 4qc..4qc+3
            float4 w = reinterpret_cast<const float4*>(W1 + (kc + kr) * HID)[qc];
            float ww[4] = {w.x, w.y, w.z, w.w};
            int kstep = kr >> 3, kk = kr & 7;
#pragma unroll
            for (int j = 0; j < 4; j++) {
                int c = 4 * qc + j;
                int nt = c >> 3, nn = c & 7;
                int lt = (nn << 2) | (kk & 3);
                int idx = kk >> 2;
                sB[(((nt << 2) | kstep) << 6) + (lt << 1) + idx] = to_tf32(ww[j]);
            }
        }
        __syncthreads();

#pragma unroll
        for (int kstep = 0; kstep < 4; kstep++) {
            uint32_t a[2][4];
#pragma unroll
            for (int fm = 0; fm < 2; fm++) {
                int mt = warp_m * 2 + fm;
                const uint4* p = reinterpret_cast<const uint4*>(
                    sA + (((mt << 2) | kstep) << 7) + (lane << 2));
                uint4 v = *p;
                a[fm][0] = v.x; a[fm][1] = v.y; a[fm][2] = v.z; a[fm][3] = v.w;
            }
            uint32_t b[4][2];
#pragma unroll
            for (int fn = 0; fn < 4; fn++) {
                int nt = warp_n * 4 + fn;
                const uint2* p = reinterpret_cast<const uint2*>(
                    sB + (((nt << 2) | kstep) << 6) + (lane << 1));
                uint2 v = *p;
                b[fn][0] = v.x; b[fn][1] = v.y;
            }
#pragma unroll
            for (int fm = 0; fm < 2; fm++)
#pragma unroll
                for (int fn = 0; fn < 4; fn++)
                    mma_tf32(acc[fm][fn], a[fm], b[fn]);
        }
    }

    // epilogue: D frag c0:(g, t*2) c1:(g, t*2+1) c2:(g+8, ..) ; g=lane>>2, t=lane&3
    int g = lane >> 2, t4 = lane & 3;
    float2 bcache[4];
#pragma unroll
    for (int fn = 0; fn < 4; fn++) {
        int nn = warp_n * 32 + fn * 8 + t4 * 2;
        bcache[fn] = make_float2(b1[nn], b1[nn + 1]);
    }
#pragma unroll
    for (int fm = 0; fm < 2; fm++) {
#pragma unroll
        for (int r = 0; r < 2; r++) {
            int m = base + warp_m * 32 + fm * 16 + g + r * 8;
            if (m >= n) continue;
            float ds = g_dis[m];
            float w = ds * ds;
#pragma unroll
            for (int fn = 0; fn < 4; fn++) {
                int nn = warp_n * 32 + fn * 8 + t4 * 2;
                float c0 = acc[fm][fn][2 * r];
                float c1 = acc[fm][fn][2 * r + 1];
                *reinterpret_cast<float2*>(g_agg1 + m * HID + nn) =
                    make_float2(c0 * w + bcache[fn].x, c1 * w + bcache[fn].y);
                *reinterpret_cast<__half2*>(g_h1h + m * HID + nn) =
                    __floats2half2_rn(c0, c1);
            }
        }
    }
}

// ---------------- layer-1 edge scatter: 16 threads/edge, fp16 gather -----

__global__ void k_edge1(const int* __restrict__ ei, int E) {
    int t = blockIdx.x * blockDim.x + threadIdx.x;
    if (t >= E * 16) return;
    int e = t >> 4, q = t & 15;
    int s = ei[e];
    int d = ei[E + e];
    float w = g_dis[s] * g_dis[d];
    const __half2* hp = reinterpret_cast<const __half2*>(g_h1h + s * HID + q * 4);
    __half2 p0 = hp[0], p1 = hp[1];
    float2 f0 = __half22float2(p0), f1 = __half22float2(p1);
    red_add_v4(g_agg1 + d * HID + q * 4,
               make_float4(w * f0.x, w * f0.y, w * f1.x, w * f1.y));
}

// ---------------- GEMM2: h2 = relu(agg1)@W2; out = dis^2*h2 + b2; h2h ----
// 128 nodes x 32 ch / block, 256 thr, f32x2 K-pairing, relu fused at stage.

__global__ __launch_bounds__(256) void k_gemm2(const float* __restrict__ W2,
                                               const float* __restrict__ b2,
                                               float* __restrict__ out, int n) {
    __shared__ float sx[128 * 66];
    __shared__ float sWp[(HID / 2) * 64];

    int tid = threadIdx.x;
    int base = blockIdx.x * 128;
    int ng = tid & 31;
    int cg = tid >> 5;

#pragma unroll
    for (int i = 0; i < 8; i++) {
        int idx = tid + 256 * i;
        int k = idx >> 5, c = idx & 31;
        sWp[(k >> 1) * 64 + c * 2 + (k & 1)] = W2[k * OUTC + c];
    }
#pragma unroll
    for (int i = 0; i < 8; i++) {
        int f = tid + 256 * i;
        int node = f >> 4;
        int q = f & 15;
        int gn = base + node;
        float4 v = make_float4(0.f, 0.f, 0.f, 0.f);
        if (gn < n) {
            v = reinterpret_cast<const float4*>(g_agg1 + gn * HID)[q];
            v.x = fmaxf(v.x, 0.f); v.y = fmaxf(v.y, 0.f);
            v.z = fmaxf(v.z, 0.f); v.w = fmaxf(v.w, 0.f);
        }
        float* r = sx + node * 66 + 4 * q;
        r[0] = v.x; r[1] = v.y; r[2] = v.z; r[3] = v.w;
    }
    __syncthreads();

    ull acc[4][4];
#pragma unroll
    for (int i = 0; i < 4; i++)
#pragma unroll
        for (int j = 0; j < 4; j++) acc[i][j] = 0ull;

#pragma unroll
    for (int k2 = 0; k2 < HID / 2; k2++) {
        ull xv0 = *reinterpret_cast<const ull*>(sx + ng * 66 + 2 * k2);
        ull xv1 = *reinterpret_cast<const ull*>(sx + (ng + 32) * 66 + 2 * k2);
        ull xv2 = *reinterpret_cast<const ull*>(sx + (ng + 64) * 66 + 2 * k2);
        ull xv3 = *reinterpret_cast<const ull*>(sx + (ng + 96) * 66 + 2 * k2);
        const ulonglong2* wr =
            reinterpret_cast<const ulonglong2*>(sWp + k2 * 64 + cg * 8);
        ulonglong2 wa = wr[0], wb = wr[1];
        fma2(acc[0][0], xv0, wa.x); fma2(acc[1][0], xv1, wa.x);
        fma2(acc[2][0], xv2, wa.x); fma2(acc[3][0], xv3, wa.x);
        fma2(acc[0][1], xv0, wa.y); fma2(acc[1][1], xv1, wa.y);
        fma2(acc[2][1], xv2, wa.y); fma2(acc[3][1], xv3, wa.y);
        fma2(acc[0][2], xv0, wb.x); fma2(acc[1][2], xv1, wb.x);
        fma2(acc[2][2], xv2, wb.x); fma2(acc[3][2], xv3, wb.x);
        fma2(acc[0][3], xv0, wb.y); fma2(acc[1][3], xv1, wb.y);
        fma2(acc[2][3], xv2, wb.y); fma2(acc[3][3], xv3, wb.y);
    }

    float4 bb = reinterpret_cast<const float4*>(b2 + cg * 4)[0];
#pragma unroll
    for (int i = 0; i < 4; i++) {
        int node = base + ng + 32 * i;
        if (node >= n) continue;
        float ds = g_dis[node];
        float w = ds * ds;
        float r0 = unpack_sum(acc[i][0]), r1 = unpack_sum(acc[i][1]);
        float r2 = unpack_sum(acc[i][2]), r3 = unpack_sum(acc[i][3]);
        float4* oo = reinterpret_cast<float4*>(out + node * OUTC + cg * 4);
        oo[0] = make_float4(r0 * w + bb.x, r1 * w + bb.y,
                            r2 * w + bb.z, r3 * w + bb.w);
        __half2* oh = reinterpret_cast<__half2*>(g_h2h + node * OUTC + cg * 4);
        oh[0] = __floats2half2_rn(r0, r1);
        oh[1] = __floats2half2_rn(r2, r3);
    }
}

// ---------------- layer-2 edge scatter: 8 threads/edge, fp16 gather ------

__global__ void k_edge2(const int* __restrict__ ei, float* __restrict__ out, int E) {
    int t = blockIdx.x * blockDim.x + threadIdx.x;
    if (t >= E * 8) return;
    int e = t >> 3, q = t & 7;
    int s = ei[e];
    int d = ei[E + e];
    float w = g_dis[s] * g_dis[d];
    const __half2* hp = reinterpret_cast<const __half2*>(g_h2h + s * OUTC + q * 4);
    __half2 p0 = hp[0], p1 = hp[1];
    float2 f0 = __half22float2(p0), f1 = __half22float2(p1);
    red_add_v4(out + d * OUTC + q * 4,
               make_float4(w * f0.x, w * f0.y, w * f1.x, w * f1.y));
}

// ---------------- launch ----------------

extern "C" void kernel_launch(void* const* d_in, const int* in_sizes, int n_in,
                              void* d_out, int out_size) {
    const float* x  = (const float*)d_in[0];
    const int*   ei = (const int*)  d_in[1];
    const float* W1 = (const float*)d_in[2];
    const float* b1 = (const float*)d_in[3];
    const float* W2 = (const float*)d_in[4];
    const float* b2 = (const float*)d_in[5];
    float* out = (float*)d_out;

    int N = in_sizes[0] / IN_CH;
    int E = in_sizes[1] / 2;

    const int T = 256;
    k_deg_init <<<(N + T - 1) / T, T>>>(N);
    k_deg_count<<<(E + T - 1) / T, T>>>(ei, E);
    k_dis      <<<(N + T - 1) / T, T>>>(N);

    k_gemm1<<<(N + 127) / 128, 256>>>(x, W1, b1, N);
    k_edge1<<<(E * 16 + T - 1) / T, T>>>(ei, E);

    k_gemm2<<<(N + 127) / 128, 256>>>(W2, b2, out, N);
    k_edge2<<<(E * 8 + T - 1) / T, T>>>(ei, out, E);
}

// round 10
// speedup vs baseline: 2.4369x; 1.3788x over previous
#include <cuda_runtime.h>
#include <cuda_bf16.h>
#include <cuda_fp16.h>
#include <cstdint>

// GCN 2-layer, CSR gather formulation with pre-scaled fp16 rows:
//   h1h[i] = fp16( dis[i] * (x@W1)[i] )            (gemm1)
//   agg1[d] = dis[d]*( sum_{s->d} h1h[s] + h1h[d] ) + b1
//   h2h[i] = fp16( dis[i] * (relu(agg1)@W2)[i] )   (gemm2)
//   out[d] = dis[d]*( sum_{s->d} h2h[s] + h2h[d] ) + b2

#define NMAX   100000
#define EMAX   1600000
#define IN_CH  128
#define HID    64
#define OUTC   32
#define NBLK   ((NMAX + 255) / 256)      // 391 scan blocks

typedef unsigned long long ull;

__device__ int    g_cnt[NMAX];           // in-degree (no self loop)
__device__ int    g_part[512];           // block partial sums -> inclusive prefix
__device__ int    g_off[NMAX + 1];       // CSR offsets
__device__ int    g_cur[NMAX];           // scatter cursors
__device__ int    g_csrc[EMAX];          // CSR src lists grouped by dst
__device__ float  g_dis[NMAX];           // deg^{-1/2} (deg incl self loop)
__device__ float  g_agg1[NMAX * HID];    // layer-1 aggregated (fp32)
__device__ __half g_h1h[NMAX * HID];     // dis-scaled x@W1, fp16
__device__ __half g_h2h[NMAX * OUTC];    // dis-scaled relu(agg1)@W2, fp16

// packed dual-fp32 FMA (gemm2)
__device__ __forceinline__ void fma2(ull& acc, ull a, ull b) {
    asm("fma.rn.f32x2 %0, %1, %2, %0;" : "+l"(acc) : "l"(a), "l"(b));
}
__device__ __forceinline__ float unpack_sum(ull v) {
    float2 f;
    asm("mov.b64 {%0, %1}, %2;" : "=f"(f.x), "=f"(f.y) : "l"(v));
    return f.x + f.y;
}

__device__ __forceinline__ uint32_t to_tf32(float f) {
    uint32_t r;
    asm("cvt.rna.tf32.f32 %0, %1;" : "=r"(r) : "f"(f));
    return r;
}

__device__ __forceinline__ void mma_tf32(float* d, const uint32_t* a, const uint32_t* b) {
    asm("mma.sync.aligned.m16n8k8.row.col.f32.tf32.tf32.f32 "
        "{%0,%1,%2,%3}, {%4,%5,%6,%7}, {%8,%9}, {%0,%1,%2,%3};"
        : "+f"(d[0]), "+f"(d[1]), "+f"(d[2]), "+f"(d[3])
        : "r"(a[0]), "r"(a[1]), "r"(a[2]), "r"(a[3]), "r"(b[0]), "r"(b[1]));
}

// ---------------- CSR build ----------------

__global__ void k_zero(int n) {
    int i = blockIdx.x * blockDim.x + threadIdx.x;
    if (i < n) g_cnt[i] = 0;
}

__global__ void k_count(const int* __restrict__ ei, int E) {
    int e = blockIdx.x * blockDim.x + threadIdx.x;
    if (e < E) atomicAdd(&g_cnt[ei[E + e]], 1);
}

// scan pass 1: per-block sums of g_cnt (256 per block)
__global__ __launch_bounds__(256) void k_scan1(int n) {
    __shared__ int s[256];
    int t = threadIdx.x;
    int i = blockIdx.x * 256 + t;
    s[t] = (i < n) ? g_cnt[i] : 0;
    __syncthreads();
#pragma unroll
    for (int st = 128; st > 0; st >>= 1) {
        if (t < st) s[t] += s[t + st];
        __syncthreads();
    }
    if (t == 0) g_part[blockIdx.x] = s[0];
}

// scan pass 2: single block, inclusive scan of block partials
__global__ __launch_bounds__(512) void k_scan2(int nb) {
    __shared__ int s[512];
    int t = threadIdx.x;
    s[t] = (t < nb) ? g_part[t] : 0;
    __syncthreads();
#pragma unroll
    for (int ofs = 1; ofs < 512; ofs <<= 1) {
        int v = (t >= ofs) ? s[t - ofs] : 0;
        __syncthreads();
        s[t] += v;
        __syncthreads();
    }
    g_part[t] = s[t];
}

// scan pass 3: offsets = block base + in-block exclusive scan; also dis
__global__ __launch_bounds__(256) void k_scan3(int n) {
    __shared__ int s[256];
    int t = threadIdx.x;
    int i = blockIdx.x * 256 + t;
    int c = (i < n) ? g_cnt[i] : 0;
    s[t] = c;
    __syncthreads();
#pragma unroll
    for (int ofs = 1; ofs < 256; ofs <<= 1) {
        int v = (t >= ofs) ? s[t - ofs] : 0;
        __syncthreads();
        s[t] += v;
        __syncthreads();
    }
    int basep = blockIdx.x ? g_part[blockIdx.x - 1] : 0;
    if (i < n) {
        int off = basep + s[t] - c;
        g_off[i] = off;
        g_cur[i] = off;
        g_dis[i] = rsqrtf((float)(c + 1));
        if (i == n - 1) g_off[n] = basep + s[t];
    }
}

__global__ void k_scatter(const int* __restrict__ ei, int E) {
    int e = blockIdx.x * blockDim.x + threadIdx.x;
    if (e < E) {
        int s = ei[e];
        int d = ei[E + e];
        int pos = atomicAdd(&g_cur[d], 1);
        g_csrc[pos] = s;
    }
}

// ---------------- GEMM1 (tf32 tensor core): h1h = fp16(dis * x@W1) -------
// CTA: 128 nodes x 64 ch, K chunked by 32. 8 warps 4(M)x2(N), warp 32x32.

#define KCT 32

__global__ __launch_bounds__(256) void k_gemm1(const float* __restrict__ x,
                                               const float* __restrict__ W1,
                                               int n) {
    __shared__ uint32_t sA[8 * 4 * 32 * 4];   // 16 KB
    __shared__ uint32_t sB[8 * 4 * 32 * 2];   // 8 KB

    int tid = threadIdx.x;
    int lane = tid & 31;
    int wid = tid >> 5;
    int warp_m = wid & 3;
    int warp_n = wid >> 2;
    int base = blockIdx.x * 128;

    float acc[2][4][4];
#pragma unroll
    for (int fm = 0; fm < 2; fm++)
#pragma unroll
        for (int fn = 0; fn < 4; fn++)
#pragma unroll
            for (int r = 0; r < 4; r++) acc[fm][fn][r] = 0.f;

    for (int kc = 0; kc < IN_CH; kc += KCT) {
        __syncthreads();
#pragma unroll
        for (int i = 0; i < 4; i++) {
            int f = tid + 256 * i;
            int node = f >> 3;
            int q = f & 7;
            int gn = base + node;
            float4 v = make_float4(0.f, 0.f, 0.f, 0.f);
            if (gn < n) v = reinterpret_cast<const float4*>(x + gn * IN_CH + kc)[q];
            float vv[4] = {v.x, v.y, v.z, v.w};
            int mt = node >> 4, mm = node & 15;
#pragma unroll
            for (int j = 0; j < 4; j++) {
                int k = 4 * q + j;
                int kstep = k >> 3, kk = k & 7;
                int lt = ((mm & 7) << 2) | (kk & 3);
                int idx = (mm >> 3) | ((kk >> 2) << 1);
                sA[(((mt << 2) | kstep) << 7) + (lt << 2) + idx] = to_tf32(vv[j]);
            }
        }
#pragma unroll
        for (int i = 0; i < 2; i++) {
            int f = tid + 256 * i;
            int kr = f >> 4;
            int qc = f & 15;
            float4 w = reinterpret_cast<const float4*>(W1 + (kc + kr) * HID)[qc];
            float ww[4] = {w.x, w.y, w.z, w.w};
            int kstep = kr >> 3, kk = kr & 7;
#pragma unroll
            for (int j = 0; j < 4; j++) {
                int c = 4 * qc + j;
                int nt = c >> 3, nn = c & 7;
                int lt = (nn << 2) | (kk & 3);
                int idx = kk >> 2;
                sB[(((nt << 2) | kstep) << 6) + (lt << 1) + idx] = to_tf32(ww[j]);
            }
        }
        __syncthreads();

#pragma unroll
        for (int kstep = 0; kstep < 4; kstep++) {
            uint32_t a[2][4];
#pragma unroll
            for (int fm = 0; fm < 2; fm++) {
                int mt = warp_m * 2 + fm;
                uint4 v = *reinterpret_cast<const uint4*>(
                    sA + (((mt << 2) | kstep) << 7) + (lane << 2));
                a[fm][0] = v.x; a[fm][1] = v.y; a[fm][2] = v.z; a[fm][3] = v.w;
            }
            uint32_t b[4][2];
#pragma unroll
            for (int fn = 0; fn < 4; fn++) {
                int nt = warp_n * 4 + fn;
                uint2 v = *reinterpret_cast<const uint2*>(
                    sB + (((nt << 2) | kstep) << 6) + (lane << 1));
                b[fn][0] = v.x; b[fn][1] = v.y;
            }
#pragma unroll
            for (int fm = 0; fm < 2; fm++)
#pragma unroll
                for (int fn = 0; fn < 4; fn++)
                    mma_tf32(acc[fm][fn], a[fm], b[fn]);
        }
    }

    int g = lane >> 2, t4 = lane & 3;
#pragma unroll
    for (int fm = 0; fm < 2; fm++) {
#pragma unroll
        for (int r = 0; r < 2; r++) {
            int m = base + warp_m * 32 + fm * 16 + g + r * 8;
            if (m >= n) continue;
            float ds = g_dis[m];
#pragma unroll
            for (int fn = 0; fn < 4; fn++) {
                int nn = warp_n * 32 + fn * 8 + t4 * 2;
                float c0 = acc[fm][fn][2 * r] * ds;
                float c1 = acc[fm][fn][2 * r + 1] * ds;
                *reinterpret_cast<__half2*>(g_h1h + m * HID + nn) =
                    __floats2half2_rn(c0, c1);
            }
        }
    }
}

// ---------------- layer-1 aggregation: warp per dst, gather --------------
// agg1[d] = dd*( sum_s h1h[s] + h1h[d] ) + b1 ; lane covers 2 ch (half2).

__global__ __launch_bounds__(256) void k_agg1(const float* __restrict__ b1, int n) {
    int d = (blockIdx.x * blockDim.x + threadIdx.x) >> 5;
    int lane = threadIdx.x & 31;
    if (d >= n) return;
    int lo = g_off[d], hi = g_off[d + 1];
    float dd = g_dis[d];

    // self term (scaled row d)
    float2 acc = __half22float2(
        reinterpret_cast<const __half2*>(g_h1h + d * HID)[lane]);

    for (int jb = lo; jb < hi; jb += 32) {
        int myidx = (jb + lane < hi) ? g_csrc[jb + lane] : 0;
        int cnt = min(32, hi - jb);
        int kk = 0;
        for (; kk + 8 <= cnt; kk += 8) {
            int s0 = __shfl_sync(0xffffffffu, myidx, kk + 0);
            int s1 = __shfl_sync(0xffffffffu, myidx, kk + 1);
            int s2 = __shfl_sync(0xffffffffu, myidx, kk + 2);
            int s3 = __shfl_sync(0xffffffffu, myidx, kk + 3);
            int s4 = __shfl_sync(0xffffffffu, myidx, kk + 4);
            int s5 = __shfl_sync(0xffffffffu, myidx, kk + 5);
            int s6 = __shfl_sync(0xffffffffu, myidx, kk + 6);
            int s7 = __shfl_sync(0xffffffffu, myidx, kk + 7);
            __half2 v0 = reinterpret_cast<const __half2*>(g_h1h + s0 * HID)[lane];
            __half2 v1 = reinterpret_cast<const __half2*>(g_h1h + s1 * HID)[lane];
            __half2 v2 = reinterpret_cast<const __half2*>(g_h1h + s2 * HID)[lane];
            __half2 v3 = reinterpret_cast<const __half2*>(g_h1h + s3 * HID)[lane];
            __half2 v4 = reinterpret_cast<const __half2*>(g_h1h + s4 * HID)[lane];
            __half2 v5 = reinterpret_cast<const __half2*>(g_h1h + s5 * HID)[lane];
            __half2 v6 = reinterpret_cast<const __half2*>(g_h1h + s6 * HID)[lane];
            __half2 v7 = reinterpret_cast<const __half2*>(g_h1h + s7 * HID)[lane];
            float2 f0 = __half22float2(v0), f1 = __half22float2(v1);
            float2 f2 = __half22float2(v2), f3 = __half22float2(v3);
            float2 f4 = __half22float2(v4), f5 = __half22float2(v5);
            float2 f6 = __half22float2(v6), f7 = __half22float2(v7);
            acc.x += ((f0.x + f1.x) + (f2.x + f3.x)) + ((f4.x + f5.x) + (f6.x + f7.x));
            acc.y += ((f0.y + f1.y) + (f2.y + f3.y)) + ((f4.y + f5.y) + (f6.y + f7.y));
        }
        for (; kk < cnt; kk++) {
            int s0 = __shfl_sync(0xffffffffu, myidx, kk);
            float2 f0 = __half22float2(
                reinterpret_cast<const __half2*>(g_h1h + s0 * HID)[lane]);
            acc.x += f0.x;
            acc.y += f0.y;
        }
    }

    float2 bb = reinterpret_cast<const float2*>(b1)[lane];
    *reinterpret_cast<float2*>(g_agg1 + d * HID + lane * 2) =
        make_float2(acc.x * dd + bb.x, acc.y * dd + bb.y);
}

// ---------------- GEMM2: h2h = fp16(dis * relu(agg1)@W2) -----------------
// 128 nodes x 32 ch / block, 256 thr, f32x2 K-pairing, relu fused at stage.

__global__ __launch_bounds__(256) void k_gemm2(const float* __restrict__ W2, int n) {
    __shared__ float sx[128 * 66];
    __shared__ float sWp[(HID / 2) * 64];

    int tid = threadIdx.x;
    int base = blockIdx.x * 128;
    int ng = tid & 31;
    int cg = tid >> 5;

#pragma unroll
    for (int i = 0; i < 8; i++) {
        int idx = tid + 256 * i;
        int k = idx >> 5, c = idx & 31;
        sWp[(k >> 1) * 64 + c * 2 + (k & 1)] = W2[k * OUTC + c];
    }
#pragma unroll
    for (int i = 0; i < 8; i++) {
        int f = tid + 256 * i;
        int node = f >> 4;
        int q = f & 15;
        int gn = base + node;
        float4 v = make_float4(0.f, 0.f, 0.f, 0.f);
        if (gn < n) {
            v = reinterpret_cast<const float4*>(g_agg1 + gn * HID)[q];
            v.x = fmaxf(v.x, 0.f); v.y = fmaxf(v.y, 0.f);
            v.z = fmaxf(v.z, 0.f); v.w = fmaxf(v.w, 0.f);
        }
        float* r = sx + node * 66 + 4 * q;
        r[0] = v.x; r[1] = v.y; r[2] = v.z; r[3] = v.w;
    }
    __syncthreads();

    ull acc[4][4];
#pragma unroll
    for (int i = 0; i < 4; i++)
#pragma unroll
        for (int j = 0; j < 4; j++) acc[i][j] = 0ull;

#pragma unroll
    for (int k2 = 0; k2 < HID / 2; k2++) {
        ull xv0 = *reinterpret_cast<const ull*>(sx + ng * 66 + 2 * k2);
        ull xv1 = *reinterpret_cast<const ull*>(sx + (ng + 32) * 66 + 2 * k2);
        ull xv2 = *reinterpret_cast<const ull*>(sx + (ng + 64) * 66 + 2 * k2);
        ull xv3 = *reinterpret_cast<const ull*>(sx + (ng + 96) * 66 + 2 * k2);
        const ulonglong2* wr =
            reinterpret_cast<const ulonglong2*>(sWp + k2 * 64 + cg * 8);
        ulonglong2 wa = wr[0], wb = wr[1];
        fma2(acc[0][0], xv0, wa.x); fma2(acc[1][0], xv1, wa.x);
        fma2(acc[2][0], xv2, wa.x); fma2(acc[3][0], xv3, wa.x);
        fma2(acc[0][1], xv0, wa.y); fma2(acc[1][1], xv1, wa.y);
        fma2(acc[2][1], xv2, wa.y); fma2(acc[3][1], xv3, wa.y);
        fma2(acc[0][2], xv0, wb.x); fma2(acc[1][2], xv1, wb.x);
        fma2(acc[2][2], xv2, wb.x); fma2(acc[3][2], xv3, wb.x);
        fma2(acc[0][3], xv0, wb.y); fma2(acc[1][3], xv1, wb.y);
        fma2(acc[2][3], xv2, wb.y); fma2(acc[3][3], xv3, wb.y);
    }

#pragma unroll
    for (int i = 0; i < 4; i++) {
        int node = base + ng + 32 * i;
        if (node >= n) continue;
        float ds = g_dis[node];
        float r0 = unpack_sum(acc[i][0]) * ds, r1 = unpack_sum(acc[i][1]) * ds;
        float r2 = unpack_sum(acc[i][2]) * ds, r3 = unpack_sum(acc[i][3]) * ds;
        __half2* oh = reinterpret_cast<__half2*>(g_h2h + node * OUTC + cg * 4);
        oh[0] = __floats2half2_rn(r0, r1);
        oh[1] = __floats2half2_rn(r2, r3);
    }
}

// ---------------- layer-2 aggregation: warp per dst, gather --------------
// out[d] = dd*( sum_s h2h[s] + h2h[d] ) + b2 ; lane covers 1 ch.

__global__ __launch_bounds__(256) void k_agg2(const float* __restrict__ b2,
                                              float* __restrict__ out, int n) {
    int d = (blockIdx.x * blockDim.x + threadIdx.x) >> 5;
    int lane = threadIdx.x & 31;
    if (d >= n) return;
    int lo = g_off[d], hi = g_off[d + 1];
    float dd = g_dis[d];

    float acc = __half2float(g_h2h[d * OUTC + lane]);

    for (int jb = lo; jb < hi; jb += 32) {
        int myidx = (jb + lane < hi) ? g_csrc[jb + lane] : 0;
        int cnt = min(32, hi - jb);
        int kk = 0;
        for (; kk + 8 <= cnt; kk += 8) {
            int s0 = __shfl_sync(0xffffffffu, myidx, kk + 0);
            int s1 = __shfl_sync(0xffffffffu, myidx, kk + 1);
            int s2 = __shfl_sync(0xffffffffu, myidx, kk + 2);
            int s3 = __shfl_sync(0xffffffffu, myidx, kk + 3);
            int s4 = __shfl_sync(0xffffffffu, myidx, kk + 4);
            int s5 = __shfl_sync(0xffffffffu, myidx, kk + 5);
            int s6 = __shfl_sync(0xffffffffu, myidx, kk + 6);
            int s7 = __shfl_sync(0xffffffffu, myidx, kk + 7);
            float f0 = __half2float(g_h2h[s0 * OUTC + lane]);
            float f1 = __half2float(g_h2h[s1 * OUTC + lane]);
            float f2 = __half2float(g_h2h[s2 * OUTC + lane]);
            float f3 = __half2float(g_h2h[s3 * OUTC + lane]);
            float f4 = __half2float(g_h2h[s4 * OUTC + lane]);
            float f5 = __half2float(g_h2h[s5 * OUTC + lane]);
            float f6 = __half2float(g_h2h[s6 * OUTC + lane]);
            float f7 = __half2float(g_h2h[s7 * OUTC + lane]);
            acc += ((f0 + f1) + (f2 + f3)) + ((f4 + f5) + (f6 + f7));
        }
        for (; kk < cnt; kk++) {
            int s0 = __shfl_sync(0xffffffffu, myidx, kk);
            acc += __half2float(g_h2h[s0 * OUTC + lane]);
        }
    }

    out[d * OUTC + lane] = acc * dd + b2[lane];
}

// ---------------- launch ----------------

extern "C" void kernel_launch(void* const* d_in, const int* in_sizes, int n_in,
                              void* d_out, int out_size) {
    const float* x  = (const float*)d_in[0];
    const int*   ei = (const int*)  d_in[1];
    const float* W1 = (const float*)d_in[2];
    const float* b1 = (const float*)d_in[3];
    const float* W2 = (const float*)d_in[4];
    const float* b2 = (const float*)d_in[5];
    float* out = (float*)d_out;

    int N = in_sizes[0] / IN_CH;
    int E = in_sizes[1] / 2;
    int nb = (N + 255) / 256;

    const int T = 256;
    k_zero   <<<(N + T - 1) / T, T>>>(N);
    k_count  <<<(E + T - 1) / T, T>>>(ei, E);
    k_scan1  <<<nb, 256>>>(N);
    k_scan2  <<<1, 512>>>(nb);
    k_scan3  <<<nb, 256>>>(N);
    k_scatter<<<(E + T - 1) / T, T>>>(ei, E);

    k_gemm1<<<(N + 127) / 128, 256>>>(x, W1, N);
    k_agg1 <<<(N * 32 + T - 1) / T, T>>>(b1, N);

    k_gemm2<<<(N + 127) / 128, 256>>>(W2, N);
    k_agg2 <<<(N * 32 + T - 1) / T, T>>>(b2, out, N);
}

// round 11
// speedup vs baseline: 2.6451x; 1.0854x over previous
#include <cuda_runtime.h>
#include <cuda_bf16.h>
#include <cuda_fp16.h>
#include <cstdint>

// GCN 2-layer, CSR gather formulation with pre-scaled fp16 rows.
// Fork-join graph: gemm1 (needs only dis) overlaps the CSR scan/scatter.

#define NMAX   100000
#define EMAX   1600000
#define IN_CH  128
#define HID    64
#define OUTC   32

typedef unsigned long long ull;

__device__ int    g_cnt[NMAX];           // in-degree (no self loop)
__device__ int    g_part[512];           // block partials -> inclusive prefix
__device__ int    g_off[NMAX + 1];       // CSR offsets
__device__ int    g_cur[NMAX];           // scatter cursors
__device__ int    g_csrc[EMAX];          // CSR src lists grouped by dst
__device__ float  g_dis[NMAX];           // deg^{-1/2} (deg incl self loop)
__device__ float  g_agg1[NMAX * HID];    // layer-1 aggregated (fp32)
__device__ __half g_h1h[NMAX * HID];     // dis-scaled x@W1, fp16
__device__ __half g_h2h[NMAX * OUTC];    // dis-scaled relu(agg1)@W2, fp16

// packed dual-fp32 FMA (gemm2)
__device__ __forceinline__ void fma2(ull& acc, ull a, ull b) {
    asm("fma.rn.f32x2 %0, %1, %2, %0;" : "+l"(acc) : "l"(a), "l"(b));
}
__device__ __forceinline__ float unpack_sum(ull v) {
    float2 f;
    asm("mov.b64 {%0, %1}, %2;" : "=f"(f.x), "=f"(f.y) : "l"(v));
    return f.x + f.y;
}

__device__ __forceinline__ uint32_t to_tf32(float f) {
    uint32_t r;
    asm("cvt.rna.tf32.f32 %0, %1;" : "=r"(r) : "f"(f));
    return r;
}

__device__ __forceinline__ void mma_tf32(float* d, const uint32_t* a, const uint32_t* b) {
    asm("mma.sync.aligned.m16n8k8.row.col.f32.tf32.tf32.f32 "
        "{%0,%1,%2,%3}, {%4,%5,%6,%7}, {%8,%9}, {%0,%1,%2,%3};"
        : "+f"(d[0]), "+f"(d[1]), "+f"(d[2]), "+f"(d[3])
        : "r"(a[0]), "r"(a[1]), "r"(a[2]), "r"(a[3]), "r"(b[0]), "r"(b[1]));
}

// ---------------- CSR build ----------------

__global__ void k_zero(int n) {
    int i = blockIdx.x * blockDim.x + threadIdx.x;
    if (i < n) g_cnt[i] = 0;
}

__global__ void k_count(const int* __restrict__ ei, int E) {
    int e = blockIdx.x * blockDim.x + threadIdx.x;
    if (e < E) atomicAdd(&g_cnt[ei[E + e]], 1);
}

__global__ void k_dis(int n) {
    int i = blockIdx.x * blockDim.x + threadIdx.x;
    if (i < n) g_dis[i] = rsqrtf((float)(g_cnt[i] + 1));
}

// scan pass 1: per-block sums of g_cnt (256 per block)
__global__ __launch_bounds__(256) void k_scan1(int n) {
    __shared__ int s[256];
    int t = threadIdx.x;
    int i = blockIdx.x * 256 + t;
    s[t] = (i < n) ? g_cnt[i] : 0;
    __syncthreads();
#pragma unroll
    for (int st = 128; st > 0; st >>= 1) {
        if (t < st) s[t] += s[t + st];
        __syncthreads();
    }
    if (t == 0) g_part[blockIdx.x] = s[0];
}

// scan pass 2: single block 512 thr, warp-shuffle inclusive scan of partials
__global__ __launch_bounds__(512) void k_scan2(int nb) {
    __shared__ int warp_sum[16];
    int t = threadIdx.x;
    int lane = t & 31, w = t >> 5;
    int v = (t < nb) ? g_part[t] : 0;
#pragma unroll
    for (int ofs = 1; ofs < 32; ofs <<= 1) {
        int u = __shfl_up_sync(0xffffffffu, v, ofs);
        if (lane >= ofs) v += u;
    }
    if (lane == 31) warp_sum[w] = v;
    __syncthreads();
    if (w == 0) {
        int ws = (lane < 16) ? warp_sum[lane] : 0;
#pragma unroll
        for (int ofs = 1; ofs < 16; ofs <<= 1) {
            int u = __shfl_up_sync(0xffffffffu, ws, ofs);
            if (lane >= ofs) ws += u;
        }
        if (lane < 16) warp_sum[lane] = ws;
    }
    __syncthreads();
    if (w > 0) v += warp_sum[w - 1];
    g_part[t] = v;
}

// scan pass 3: offsets = block base + in-block exclusive scan
__global__ __launch_bounds__(256) void k_scan3(int n) {
    __shared__ int s[256];
    int t = threadIdx.x;
    int i = blockIdx.x * 256 + t;
    int c = (i < n) ? g_cnt[i] : 0;
    s[t] = c;
    __syncthreads();
#pragma unroll
    for (int ofs = 1; ofs < 256; ofs <<= 1) {
        int v = (t >= ofs) ? s[t - ofs] : 0;
        __syncthreads();
        s[t] += v;
        __syncthreads();
    }
    int basep = blockIdx.x ? g_part[blockIdx.x - 1] : 0;
    if (i < n) {
        int off = basep + s[t] - c;
        g_off[i] = off;
        g_cur[i] = off;
        if (i == n - 1) g_off[n] = basep + s[t];
    }
}

__global__ void k_scatter(const int* __restrict__ ei, int E) {
    int e = blockIdx.x * blockDim.x + threadIdx.x;
    if (e < E) {
        int s = ei[e];
        int d = ei[E + e];
        int pos = atomicAdd(&g_cur[d], 1);
        g_csrc[pos] = s;
    }
}

// ---------------- GEMM1 (tf32 tensor core): h1h = fp16(dis * x@W1) -------
// CTA: 128 nodes x 64 ch, K chunked by 32. 8 warps 4(M)x2(N), warp 32x32.

#define KCT 32

__global__ __launch_bounds__(256) void k_gemm1(const float* __restrict__ x,
                                               const float* __restrict__ W1,
                                               int n) {
    __shared__ uint32_t sA[8 * 4 * 32 * 4];   // 16 KB
    __shared__ uint32_t sB[8 * 4 * 32 * 2];   // 8 KB

    int tid = threadIdx.x;
    int lane = tid & 31;
    int wid = tid >> 5;
    int warp_m = wid & 3;
    int warp_n = wid >> 2;
    int base = blockIdx.x * 128;

    float acc[2][4][4];
#pragma unroll
    for (int fm = 0; fm < 2; fm++)
#pragma unroll
        for (int fn = 0; fn < 4; fn++)
#pragma unroll
            for (int r = 0; r < 4; r++) acc[fm][fn][r] = 0.f;

    for (int kc = 0; kc < IN_CH; kc += KCT) {
        __syncthreads();
#pragma unroll
        for (int i = 0; i < 4; i++) {
            int f = tid + 256 * i;
            int node = f >> 3;
            int q = f & 7;
            int gn = base + node;
            float4 v = make_float4(0.f, 0.f, 0.f, 0.f);
            if (gn < n) v = reinterpret_cast<const float4*>(x + gn * IN_CH + kc)[q];
            float vv[4] = {v.x, v.y, v.z, v.w};
            int mt = node >> 4, mm = node & 15;
#pragma unroll
            for (int j = 0; j < 4; j++) {
                int k = 4 * q + j;
                int kstep = k >> 3, kk = k & 7;
                int lt = ((mm & 7) << 2) | (kk & 3);
                int idx = (mm >> 3) | ((kk >> 2) << 1);
                sA[(((mt << 2) | kstep) << 7) + (lt << 2) + idx] = to_tf32(vv[j]);
            }
        }
#pragma unroll
        for (int i = 0; i < 2; i++) {
            int f = tid + 256 * i;
            int kr = f >> 4;
            int qc = f & 15;
            float4 w = reinterpret_cast<const float4*>(W1 + (kc + kr) * HID)[qc];
            float ww[4] = {w.x, w.y, w.z, w.w};
            int kstep = kr >> 3, kk = kr & 7;
#pragma unroll
            for (int j = 0; j < 4; j++) {
                int c = 4 * qc + j;
                int nt = c >> 3, nn = c & 7;
                int lt = (nn << 2) | (kk & 3);
                int idx = kk >> 2;
                sB[(((nt << 2) | kstep) << 6) + (lt << 1) + idx] = to_tf32(ww[j]);
            }
        }
        __syncthreads();

#pragma unroll
        for (int kstep = 0; kstep < 4; kstep++) {
            uint32_t a[2][4];
#pragma unroll
            for (int fm = 0; fm < 2; fm++) {
                int mt = warp_m * 2 + fm;
                uint4 v = *reinterpret_cast<const uint4*>(
                    sA + (((mt << 2) | kstep) << 7) + (lane << 2));
                a[fm][0] = v.x; a[fm][1] = v.y; a[fm][2] = v.z; a[fm][3] = v.w;
            }
            uint32_t b[4][2];
#pragma unroll
            for (int fn = 0; fn < 4; fn++) {
                int nt = warp_n * 4 + fn;
                uint2 v = *reinterpret_cast<const uint2*>(
                    sB + (((nt << 2) | kstep) << 6) + (lane << 1));
                b[fn][0] = v.x; b[fn][1] = v.y;
            }
#pragma unroll
            for (int fm = 0; fm < 2; fm++)
#pragma unroll
                for (int fn = 0; fn < 4; fn++)
                    mma_tf32(acc[fm][fn], a[fm], b[fn]);
        }
    }

    int g = lane >> 2, t4 = lane & 3;
#pragma unroll
    for (int fm = 0; fm < 2; fm++) {
#pragma unroll
        for (int r = 0; r < 2; r++) {
            int m = base + warp_m * 32 + fm * 16 + g + r * 8;
            if (m >= n) continue;
            float ds = g_dis[m];
#pragma unroll
            for (int fn = 0; fn < 4; fn++) {
                int nn = warp_n * 32 + fn * 8 + t4 * 2;
                float c0 = acc[fm][fn][2 * r] * ds;
                float c1 = acc[fm][fn][2 * r + 1] * ds;
                *reinterpret_cast<__half2*>(g_h1h + m * HID + nn) =
                    __floats2half2_rn(c0, c1);
            }
        }
    }
}

// ---------------- layer-1 aggregation: warp per dst, gather --------------

__global__ __launch_bounds__(256) void k_agg1(const float* __restrict__ b1, int n) {
    int d = (blockIdx.x * blockDim.x + threadIdx.x) >> 5;
    int lane = threadIdx.x & 31;
    if (d >= n) return;
    int lo = g_off[d], hi = g_off[d + 1];
    float dd = g_dis[d];

    float2 acc = __half22float2(
        reinterpret_cast<const __half2*>(g_h1h + d * HID)[lane]);

    for (int jb = lo; jb < hi; jb += 32) {
        int myidx = (jb + lane < hi) ? g_csrc[jb + lane] : 0;
        int cnt = min(32, hi - jb);
        int kk = 0;
        for (; kk + 8 <= cnt; kk += 8) {
            int s0 = __shfl_sync(0xffffffffu, myidx, kk + 0);
            int s1 = __shfl_sync(0xffffffffu, myidx, kk + 1);
            int s2 = __shfl_sync(0xffffffffu, myidx, kk + 2);
            int s3 = __shfl_sync(0xffffffffu, myidx, kk + 3);
            int s4 = __shfl_sync(0xffffffffu, myidx, kk + 4);
            int s5 = __shfl_sync(0xffffffffu, myidx, kk + 5);
            int s6 = __shfl_sync(0xffffffffu, myidx, kk + 6);
            int s7 = __shfl_sync(0xffffffffu, myidx, kk + 7);
            __half2 v0 = reinterpret_cast<const __half2*>(g_h1h + s0 * HID)[lane];
            __half2 v1 = reinterpret_cast<const __half2*>(g_h1h + s1 * HID)[lane];
            __half2 v2 = reinterpret_cast<const __half2*>(g_h1h + s2 * HID)[lane];
            __half2 v3 = reinterpret_cast<const __half2*>(g_h1h + s3 * HID)[lane];
            __half2 v4 = reinterpret_cast<const __half2*>(g_h1h + s4 * HID)[lane];
            __half2 v5 = reinterpret_cast<const __half2*>(g_h1h + s5 * HID)[lane];
            __half2 v6 = reinterpret_cast<const __half2*>(g_h1h + s6 * HID)[lane];
            __half2 v7 = reinterpret_cast<const __half2*>(g_h1h + s7 * HID)[lane];
            float2 f0 = __half22float2(v0), f1 = __half22float2(v1);
            float2 f2 = __half22float2(v2), f3 = __half22float2(v3);
            float2 f4 = __half22float2(v4), f5 = __half22float2(v5);
            float2 f6 = __half22float2(v6), f7 = __half22float2(v7);
            acc.x += ((f0.x + f1.x) + (f2.x + f3.x)) + ((f4.x + f5.x) + (f6.x + f7.x));
            acc.y += ((f0.y + f1.y) + (f2.y + f3.y)) + ((f4.y + f5.y) + (f6.y + f7.y));
        }
        for (; kk < cnt; kk++) {
            int s0 = __shfl_sync(0xffffffffu, myidx, kk);
            float2 f0 = __half22float2(
                reinterpret_cast<const __half2*>(g_h1h + s0 * HID)[lane]);
            acc.x += f0.x;
            acc.y += f0.y;
        }
    }

    float2 bb = reinterpret_cast<const float2*>(b1)[lane];
    *reinterpret_cast<float2*>(g_agg1 + d * HID + lane * 2) =
        make_float2(acc.x * dd + bb.x, acc.y * dd + bb.y);
}

// ---------------- GEMM2: h2h = fp16(dis * relu(agg1)@W2) -----------------

__global__ __launch_bounds__(256) void k_gemm2(const float* __restrict__ W2, int n) {
    __shared__ float sx[128 * 66];
    __shared__ float sWp[(HID / 2) * 64];

    int tid = threadIdx.x;
    int base = blockIdx.x * 128;
    int ng = tid & 31;
    int cg = tid >> 5;

#pragma unroll
    for (int i = 0; i < 8; i++) {
        int idx = tid + 256 * i;
        int k = idx >> 5, c = idx & 31;
        sWp[(k >> 1) * 64 + c * 2 + (k & 1)] = W2[k * OUTC + c];
    }
#pragma unroll
    for (int i = 0; i < 8; i++) {
        int f = tid + 256 * i;
        int node = f >> 4;
        int q = f & 15;
        int gn = base + node;
        float4 v = make_float4(0.f, 0.f, 0.f, 0.f);
        if (gn < n) {
            v = reinterpret_cast<const float4*>(g_agg1 + gn * HID)[q];
            v.x = fmaxf(v.x, 0.f); v.y = fmaxf(v.y, 0.f);
            v.z = fmaxf(v.z, 0.f); v.w = fmaxf(v.w, 0.f);
        }
        float* r = sx + node * 66 + 4 * q;
        r[0] = v.x; r[1] = v.y; r[2] = v.z; r[3] = v.w;
    }
    __syncthreads();

    ull acc[4][4];
#pragma unroll
    for (int i = 0; i < 4; i++)
#pragma unroll
        for (int j = 0; j < 4; j++) acc[i][j] = 0ull;

#pragma unroll
    for (int k2 = 0; k2 < HID / 2; k2++) {
        ull xv0 = *reinterpret_cast<const ull*>(sx + ng * 66 + 2 * k2);
        ull xv1 = *reinterpret_cast<const ull*>(sx + (ng + 32) * 66 + 2 * k2);
        ull xv2 = *reinterpret_cast<const ull*>(sx + (ng + 64) * 66 + 2 * k2);
        ull xv3 = *reinterpret_cast<const ull*>(sx + (ng + 96) * 66 + 2 * k2);
        const ulonglong2* wr =
            reinterpret_cast<const ulonglong2*>(sWp + k2 * 64 + cg * 8);
        ulonglong2 wa = wr[0], wb = wr[1];
        fma2(acc[0][0], xv0, wa.x); fma2(acc[1][0], xv1, wa.x);
        fma2(acc[2][0], xv2, wa.x); fma2(acc[3][0], xv3, wa.x);
        fma2(acc[0][1], xv0, wa.y); fma2(acc[1][1], xv1, wa.y);
        fma2(acc[2][1], xv2, wa.y); fma2(acc[3][1], xv3, wa.y);
        fma2(acc[0][2], xv0, wb.x); fma2(acc[1][2], xv1, wb.x);
        fma2(acc[2][2], xv2, wb.x); fma2(acc[3][2], xv3, wb.x);
        fma2(acc[0][3], xv0, wb.y); fma2(acc[1][3], xv1, wb.y);
        fma2(acc[2][3], xv2, wb.y); fma2(acc[3][3], xv3, wb.y);
    }

#pragma unroll
    for (int i = 0; i < 4; i++) {
        int node = base + ng + 32 * i;
        if (node >= n) continue;
        float ds = g_dis[node];
        float r0 = unpack_sum(acc[i][0]) * ds, r1 = unpack_sum(acc[i][1]) * ds;
        float r2 = unpack_sum(acc[i][2]) * ds, r3 = unpack_sum(acc[i][3]) * ds;
        __half2* oh = reinterpret_cast<__half2*>(g_h2h + node * OUTC + cg * 4);
        oh[0] = __floats2half2_rn(r0, r1);
        oh[1] = __floats2half2_rn(r2, r3);
    }
}

// ---------------- layer-2 aggregation: warp per dst, gather --------------

__global__ __launch_bounds__(256) void k_agg2(const float* __restrict__ b2,
                                              float* __restrict__ out, int n) {
    int d = (blockIdx.x * blockDim.x + threadIdx.x) >> 5;
    int lane = threadIdx.x & 31;
    if (d >= n) return;
    int lo = g_off[d], hi = g_off[d + 1];
    float dd = g_dis[d];

    float acc = __half2float(g_h2h[d * OUTC + lane]);

    for (int jb = lo; jb < hi; jb += 32) {
        int myidx = (jb + lane < hi) ? g_csrc[jb + lane] : 0;
        int cnt = min(32, hi - jb);
        int kk = 0;
        for (; kk + 8 <= cnt; kk += 8) {
            int s0 = __shfl_sync(0xffffffffu, myidx, kk + 0);
            int s1 = __shfl_sync(0xffffffffu, myidx, kk + 1);
            int s2 = __shfl_sync(0xffffffffu, myidx, kk + 2);
            int s3 = __shfl_sync(0xffffffffu, myidx, kk + 3);
            int s4 = __shfl_sync(0xffffffffu, myidx, kk + 4);
            int s5 = __shfl_sync(0xffffffffu, myidx, kk + 5);
            int s6 = __shfl_sync(0xffffffffu, myidx, kk + 6);
            int s7 = __shfl_sync(0xffffffffu, myidx, kk + 7);
            float f0 = __half2float(g_h2h[s0 * OUTC + lane]);
            float f1 = __half2float(g_h2h[s1 * OUTC + lane]);
            float f2 = __half2float(g_h2h[s2 * OUTC + lane]);
            float f3 = __half2float(g_h2h[s3 * OUTC + lane]);
            float f4 = __half2float(g_h2h[s4 * OUTC + lane]);
            float f5 = __half2float(g_h2h[s5 * OUTC + lane]);
            float f6 = __half2float(g_h2h[s6 * OUTC + lane]);
            float f7 = __half2float(g_h2h[s7 * OUTC + lane]);
            acc += ((f0 + f1) + (f2 + f3)) + ((f4 + f5) + (f6 + f7));
        }
        for (; kk < cnt; kk++) {
            int s0 = __shfl_sync(0xffffffffu, myidx, kk);
            acc += __half2float(g_h2h[s0 * OUTC + lane]);
        }
    }

    out[d * OUTC + lane] = acc * dd + b2[lane];
}

// ---------------- launch (fork-join overlap) ----------------

extern "C" void kernel_launch(void* const* d_in, const int* in_sizes, int n_in,
                              void* d_out, int out_size) {
    const float* x  = (const float*)d_in[0];
    const int*   ei = (const int*)  d_in[1];
    const float* W1 = (const float*)d_in[2];
    const float* b1 = (const float*)d_in[3];
    const float* W2 = (const float*)d_in[4];
    const float* b2 = (const float*)d_in[5];
    float* out = (float*)d_out;

    int N = in_sizes[0] / IN_CH;
    int E = in_sizes[1] / 2;
    int nb = (N + 255) / 256;

    // side stream + events, created once (first call is outside graph capture)
    static cudaStream_t s1 = nullptr;
    static cudaEvent_t eFork = nullptr, eJoin = nullptr;
    if (!s1) {
        cudaStreamCreateWithFlags(&s1, cudaStreamNonBlocking);
        cudaEventCreateWithFlags(&eFork, cudaEventDisableTiming);
        cudaEventCreateWithFlags(&eJoin, cudaEventDisableTiming);
    }

    const int T = 256;
    k_zero   <<<(N + T - 1) / T, T>>>(N);
    k_count  <<<(E + T - 1) / T, T>>>(ei, E);

    // fork: side stream runs dis + gemm1 (depends only on counts)
    cudaEventRecord(eFork, 0);
    cudaStreamWaitEvent(s1, eFork, 0);
    k_dis  <<<(N + T - 1) / T, T, 0, s1>>>(N);
    k_gemm1<<<(N + 127) / 128, 256, 0, s1>>>(x, W1, N);
    cudaEventRecord(eJoin, s1);

    // main stream: CSR offsets + scatter (concurrent with gemm1)
    k_scan1  <<<nb, 256>>>(N);
    k_scan2  <<<1, 512>>>(nb);
    k_scan3  <<<nb, 256>>>(N);
    k_scatter<<<(E + T - 1) / T, T>>>(ei, E);

    // join: aggregation needs both CSR and h1h
    cudaStreamWaitEvent(0, eJoin, 0);

    k_agg1 <<<(N * 32 + T - 1) / T, T>>>(b1, N);
    k_gemm2<<<(N + 127) / 128, 256>>>(W2, N);
    k_agg2 <<<(N * 32 + T - 1) / T, T>>>(b2, out, N);
}